// round 3
// baseline (speedup 1.0000x reference)
#include <cuda_runtime.h>
#include <math.h>

// Problem dims
#define B_    2
#define S_    2048
#define D_    1024
#define H_    16
#define DH_   64
#define NB_   32
#define NTOK  4096          // B_*S_
#define MLP_  4096
#define DE_   96            // extended head dim: 64 (content) + 32 (bucket)
#define PADE  68            // padded row stride for transposed smem tiles

// ---------------- scratch (device globals; no allocations allowed) ----------------
__device__ float g_xln [NTOK * D_];
__device__ float g_q   [NTOK * D_];
__device__ float g_k   [NTOK * D_];
__device__ float g_v   [NTOK * D_];
__device__ float g_qe  [NTOK * H_ * DE_];
__device__ float g_ke  [NTOK * H_ * DE_];
__device__ float g_ao  [NTOK * D_];
__device__ float g_xres[NTOK * D_];
__device__ float g_yln [NTOK * D_];
__device__ float g_hbuf[NTOK * MLP_];
__device__ float g_mq  [H_ * NB_];
__device__ float g_mk  [H_ * NB_];

// ---------------- zero the loss accumulators (determinism across replays) ----------
__global__ void zero_sums_k() {
    int i = threadIdx.x;
    if (i < H_ * NB_) { g_mq[i] = 0.f; g_mk[i] = 0.f; }
}

// ---------------- layernorm: one block per token, 256 threads ----------------------
__global__ void ln_k(const float* __restrict__ in, const float* __restrict__ g,
                     const float* __restrict__ b, float* __restrict__ out) {
    int t = blockIdx.x, tid = threadIdx.x;
    const float* x = in + (size_t)t * D_;
    float v[4]; float s = 0.f, s2 = 0.f;
#pragma unroll
    for (int i = 0; i < 4; i++) { v[i] = x[tid + i * 256]; s += v[i]; s2 += v[i] * v[i]; }
#pragma unroll
    for (int o = 16; o; o >>= 1) {
        s  += __shfl_xor_sync(0xffffffffu, s,  o);
        s2 += __shfl_xor_sync(0xffffffffu, s2, o);
    }
    __shared__ float rs[8], rs2[8];
    __shared__ float mu_s, rstd_s;
    int w = tid >> 5, l = tid & 31;
    if (l == 0) { rs[w] = s; rs2[w] = s2; }
    __syncthreads();
    if (tid == 0) {
        float a = 0.f, a2 = 0.f;
        for (int i = 0; i < 8; i++) { a += rs[i]; a2 += rs2[i]; }
        float mu = a * (1.f / D_);
        float var = a2 * (1.f / D_) - mu * mu;
        mu_s = mu; rstd_s = rsqrtf(var + 1e-6f);
    }
    __syncthreads();
    float mu = mu_s, rstd = rstd_s;
    float* op = out + (size_t)t * D_;
#pragma unroll
    for (int i = 0; i < 4; i++) {
        int c = tid + i * 256;
        op[c] = (v[i] - mu) * rstd * g[c] + b[c];
    }
}

// ---------------- generic SGEMM: C[M,N] = A[M,K] * B[K,N] (+bias)(+res)(relu) ------
// 128x128 block tile, BK=16, 256 threads, 8x8 per thread.
__global__ void __launch_bounds__(256) sgemm_k(
    const float* __restrict__ A, const float* __restrict__ Bm, float* __restrict__ C,
    int M, int N, int K,
    const float* __restrict__ bias, const float* __restrict__ res, int relu)
{
    __shared__ float As[16][132];   // transposed A tile: As[kk][m], padded
    __shared__ float Bs[16][128];
    int tid = threadIdx.x, tx = tid & 15, ty = tid >> 4;
    int bm = blockIdx.y * 128, bn = blockIdx.x * 128;
    float acc[8][8];
#pragma unroll
    for (int i = 0; i < 8; i++)
#pragma unroll
        for (int j = 0; j < 8; j++) acc[i][j] = 0.f;

    for (int k0 = 0; k0 < K; k0 += 16) {
#pragma unroll
        for (int i = 0; i < 8; i++) {
            int idx = tid + i * 256; int m = idx >> 4, kk = idx & 15;
            As[kk][m] = A[(size_t)(bm + m) * K + k0 + kk];
        }
#pragma unroll
        for (int i = 0; i < 8; i++) {
            int idx = tid + i * 256; int kk = idx >> 7, n = idx & 127;
            Bs[kk][n] = Bm[(size_t)(k0 + kk) * N + bn + n];
        }
        __syncthreads();
#pragma unroll
        for (int kk = 0; kk < 16; kk++) {
            float a[8], bb[8];
            *(float4*)&a[0]  = *(const float4*)&As[kk][ty * 8];
            *(float4*)&a[4]  = *(const float4*)&As[kk][ty * 8 + 4];
            *(float4*)&bb[0] = *(const float4*)&Bs[kk][tx * 8];
            *(float4*)&bb[4] = *(const float4*)&Bs[kk][tx * 8 + 4];
#pragma unroll
            for (int i = 0; i < 8; i++)
#pragma unroll
                for (int j = 0; j < 8; j++) acc[i][j] += a[i] * bb[j];
        }
        __syncthreads();
    }
#pragma unroll
    for (int i = 0; i < 8; i++) {
        int row = bm + ty * 8 + i;
#pragma unroll
        for (int j = 0; j < 8; j++) {
            int col = bn + tx * 8 + j;
            float vv = acc[i][j];
            if (bias) vv += bias[col];
            if (res)  vv += res[(size_t)row * N + col];
            if (relu) vv = fmaxf(vv, 0.f);
            C[(size_t)row * N + col] = vv;
        }
    }
}

// ---------------- bucket softmax + extended q'/k' build + loss accumulation --------
// One warp per (token, head). 32 lanes = 32 buckets.
__global__ void build_ext_k(const float* __restrict__ Whq, const float* __restrict__ Whk) {
    int wg   = blockIdx.x * 4 + (threadIdx.x >> 5);
    int lane = threadIdx.x & 31;
    int t = wg >> 4, h = wg & 15;
    const float* q = g_q + (size_t)t * D_ + h * DH_;
    const float* k = g_k + (size_t)t * D_ + h * DH_;
    float ql = 0.f, kl = 0.f;
#pragma unroll 8
    for (int f = 0; f < DH_; f++) {
        float qv = q[f], kv = k[f];
        ql += qv * Whq[(h * DH_ + f) * NB_ + lane];
        kl += kv * Whk[(h * DH_ + f) * NB_ + lane];
    }
    float mq = ql, mk = kl;
#pragma unroll
    for (int o = 16; o; o >>= 1) {
        mq = fmaxf(mq, __shfl_xor_sync(0xffffffffu, mq, o));
        mk = fmaxf(mk, __shfl_xor_sync(0xffffffffu, mk, o));
    }
    float eq = __expf(ql - mq), ek = __expf(kl - mk);
    float sq = eq, sk = ek;
#pragma unroll
    for (int o = 16; o; o >>= 1) {
        sq += __shfl_xor_sync(0xffffffffu, sq, o);
        sk += __shfl_xor_sync(0xffffffffu, sk, o);
    }
    float qb = eq / sq, kb = ek / sk;
    float* qe = g_qe + ((size_t)t * H_ + h) * DE_;
    float* ke = g_ke + ((size_t)t * H_ + h) * DE_;
    qe[64 + lane] = 0.1f * qb;          // cluster weight folded into q'
    ke[64 + lane] = kb;
    qe[lane]      = 0.125f * q[lane];   // 1/sqrt(DH) folded into q'
    qe[lane + 32] = 0.125f * q[lane + 32];
    ke[lane]      = k[lane];
    ke[lane + 32] = k[lane + 32];
    atomicAdd(&g_mq[h * NB_ + lane], qb);
    atomicAdd(&g_mk[h * NB_ + lane], kb);
}

// ---------------- flash attention over extended vectors ----------------------------
// Block = one (b, h, q-tile of 64). 256 threads as 16x16 grid of 4x4 tiles.
__global__ void __launch_bounds__(256) fa_k() {
    extern __shared__ float sm[];
    float* QsT = sm;                        // [DE_][PADE] transposed
    float* KsT = QsT + DE_ * PADE;          // [DE_][PADE]
    float* Vs  = KsT + DE_ * PADE;          // [64][64]
    float* PsT = Vs + 64 * 64;              // [64][65] transposed P

    int tid = threadIdx.x, tx = tid & 15, ty = tid >> 4;
    int blk = blockIdx.x;
    int qt = blk & 31, h = (blk >> 5) & 15, b = blk >> 9;
    int t0 = b * S_ + qt * 64;

#pragma unroll
    for (int i = 0; i < 24; i++) {          // 64*96 = 6144 = 24*256
        int idx = tid + i * 256; int r = idx / DE_, c = idx - r * DE_;
        QsT[c * PADE + r] = g_qe[((size_t)(t0 + r) * H_ + h) * DE_ + c];
    }
    float o[4][4]; float mrow[4], lrow[4];
#pragma unroll
    for (int i = 0; i < 4; i++) {
        mrow[i] = -1e30f; lrow[i] = 0.f;
#pragma unroll
        for (int j = 0; j < 4; j++) o[i][j] = 0.f;
    }
    __syncthreads();

    for (int kt = 0; kt < S_ / 64; kt++) {
        int k0 = b * S_ + kt * 64;
#pragma unroll
        for (int i = 0; i < 24; i++) {
            int idx = tid + i * 256; int r = idx / DE_, c = idx - r * DE_;
            KsT[c * PADE + r] = g_ke[((size_t)(k0 + r) * H_ + h) * DE_ + c];
        }
#pragma unroll
        for (int i = 0; i < 16; i++) {
            int idx = tid + i * 256; int r = idx >> 6, c = idx & 63;
            Vs[r * 64 + c] = g_v[(size_t)(k0 + r) * D_ + h * DH_ + c];
        }
        __syncthreads();

        // S = Q' K'^T  (64x64x96)
        float s[4][4];
#pragma unroll
        for (int i = 0; i < 4; i++)
#pragma unroll
            for (int j = 0; j < 4; j++) s[i][j] = 0.f;
#pragma unroll 4
        for (int c = 0; c < DE_; c++) {
            float a[4], bb[4];
            *(float4*)a  = *(const float4*)&QsT[c * PADE + ty * 4];
            *(float4*)bb = *(const float4*)&KsT[c * PADE + tx * 4];
#pragma unroll
            for (int i = 0; i < 4; i++)
#pragma unroll
                for (int j = 0; j < 4; j++) s[i][j] += a[i] * bb[j];
        }

        // online softmax per row (row spread over the 16 tx lanes)
#pragma unroll
        for (int i = 0; i < 4; i++) {
            float mt = fmaxf(fmaxf(s[i][0], s[i][1]), fmaxf(s[i][2], s[i][3]));
#pragma unroll
            for (int off = 8; off; off >>= 1)
                mt = fmaxf(mt, __shfl_xor_sync(0xffffffffu, mt, off));
            float mn  = fmaxf(mrow[i], mt);
            float fac = __expf(mrow[i] - mn);
            float ps = 0.f;
#pragma unroll
            for (int j = 0; j < 4; j++) { s[i][j] = __expf(s[i][j] - mn); ps += s[i][j]; }
#pragma unroll
            for (int off = 8; off; off >>= 1)
                ps += __shfl_xor_sync(0xffffffffu, ps, off);
            lrow[i] = lrow[i] * fac + ps;
            mrow[i] = mn;
#pragma unroll
            for (int j = 0; j < 4; j++) o[i][j] *= fac;
#pragma unroll
            for (int j = 0; j < 4; j++) PsT[(tx * 4 + j) * 65 + ty * 4 + i] = s[i][j];
        }
        __syncthreads();

        // O += P V  (64x64x64)
#pragma unroll 8
        for (int kk = 0; kk < 64; kk++) {
            float a[4], bb[4];
#pragma unroll
            for (int i = 0; i < 4; i++) a[i] = PsT[kk * 65 + ty * 4 + i];
            *(float4*)bb = *(const float4*)&Vs[kk * 64 + tx * 4];
#pragma unroll
            for (int i = 0; i < 4; i++)
#pragma unroll
                for (int j = 0; j < 4; j++) o[i][j] += a[i] * bb[j];
        }
        __syncthreads();
    }

#pragma unroll
    for (int i = 0; i < 4; i++) {
        float inv = 1.f / lrow[i];
#pragma unroll
        for (int j = 0; j < 4; j++)
            g_ao[(size_t)(t0 + ty * 4 + i) * D_ + h * DH_ + tx * 4 + j] = o[i][j] * inv;
    }
}

// ---------------- auxiliary loss ----------------------------------------------------
__global__ void loss_k(float* out, int do_write) {
    int tid = threadIdx.x;  // 512 threads == H_*NB_ entries
    float vq = g_mq[tid] * (1.f / NTOK), vk = g_mk[tid] * (1.f / NTOK);
    float s = vq * vq + vk * vk;
#pragma unroll
    for (int off = 16; off; off >>= 1) s += __shfl_xor_sync(0xffffffffu, s, off);
    __shared__ float rs[16];
    if ((tid & 31) == 0) rs[tid >> 5] = s;
    __syncthreads();
    if (tid == 0) {
        float a = 0.f;
        for (int i = 0; i < 16; i++) a += rs[i];
        if (do_write) out[0] = 0.5f * NB_ * (a / H_);
    }
}

// ---------------- launch -----------------------------------------------------------
extern "C" void kernel_launch(void* const* d_in, const int* in_sizes, int n_in,
                              void* d_out, int out_size) {
    const float* inputs = (const float*)d_in[0];
    const float* ln1g   = (const float*)d_in[1];
    const float* ln1b   = (const float*)d_in[2];
    const float* Wq     = (const float*)d_in[3];
    const float* Wk     = (const float*)d_in[4];
    const float* Wv     = (const float*)d_in[5];
    const float* Whq    = (const float*)d_in[6];
    const float* Whk    = (const float*)d_in[7];
    const float* Wo     = (const float*)d_in[8];
    const float* ln2g   = (const float*)d_in[9];
    const float* ln2b   = (const float*)d_in[10];
    const float* W1     = (const float*)d_in[11];
    const float* b1     = (const float*)d_in[12];
    const float* W2     = (const float*)d_in[13];
    const float* b2     = (const float*)d_in[14];
    float* out = (float*)d_out;

    float *xln, *q, *k, *v, *ao, *xres, *yln, *hbuf;
    cudaGetSymbolAddress((void**)&xln,  g_xln);
    cudaGetSymbolAddress((void**)&q,    g_q);
    cudaGetSymbolAddress((void**)&k,    g_k);
    cudaGetSymbolAddress((void**)&v,    g_v);
    cudaGetSymbolAddress((void**)&ao,   g_ao);
    cudaGetSymbolAddress((void**)&xres, g_xres);
    cudaGetSymbolAddress((void**)&yln,  g_yln);
    cudaGetSymbolAddress((void**)&hbuf, g_hbuf);

    zero_sums_k<<<1, 512>>>();
    ln_k<<<NTOK, 256>>>(inputs, ln1g, ln1b, xln);

    dim3 gqkv(D_ / 128, NTOK / 128);   // (8, 32)
    sgemm_k<<<gqkv, 256>>>(xln, Wq, q, NTOK, D_, D_, nullptr, nullptr, 0);
    sgemm_k<<<gqkv, 256>>>(xln, Wk, k, NTOK, D_, D_, nullptr, nullptr, 0);
    sgemm_k<<<gqkv, 256>>>(xln, Wv, v, NTOK, D_, D_, nullptr, nullptr, 0);

    build_ext_k<<<NTOK * H_ / 4, 128>>>(Whq, Whk);

    int fasmem = (DE_ * PADE * 2 + 64 * 64 + 64 * 65) * (int)sizeof(float);  // ~85 KB
    cudaFuncSetAttribute(fa_k, cudaFuncAttributeMaxDynamicSharedMemorySize, fasmem);
    fa_k<<<B_ * H_ * (S_ / 64), 256, fasmem>>>();

    sgemm_k<<<gqkv, 256>>>(ao, Wo, xres, NTOK, D_, D_, nullptr, inputs, 0);
    ln_k<<<NTOK, 256>>>(xres, ln2g, ln2b, yln);

    dim3 gm1(MLP_ / 128, NTOK / 128);  // (32, 32)
    sgemm_k<<<gm1, 256>>>(yln, W1, hbuf, NTOK, MLP_, D_, b1, nullptr, 1);
    sgemm_k<<<gqkv, 256>>>(hbuf, W2, out, NTOK, D_, MLP_, b2, xres, 0);

    loss_k<<<1, 512>>>(out + (size_t)NTOK * D_, (out_size > NTOK * D_) ? 1 : 0);
}

// round 7
// speedup vs baseline: 1.8702x; 1.8702x over previous
#include <cuda_runtime.h>
#include <cuda_bf16.h>
#include <math.h>
#include <stdint.h>

// Problem dims
#define B_    2
#define S_    2048
#define D_    1024
#define H_    16
#define DH_   64
#define NB_   32
#define NTOK  4096          // B_*S_
#define MLP_  4096
#define DE_   96            // extended head dim: 64 (content) + 32 (bucket)
#define PADE  68            // padded row stride for transposed smem tiles

// ---------------- scratch (device globals; no allocations allowed) ----------------
__device__ __align__(128) float g_q   [NTOK * D_];
__device__ __align__(128) float g_k   [NTOK * D_];
__device__ __align__(128) float g_v   [NTOK * D_];
__device__ __align__(128) float g_qe  [NTOK * H_ * DE_];
__device__ __align__(128) float g_ke  [NTOK * H_ * DE_];
__device__ __align__(128) float g_xres[NTOK * D_];
__device__ float g_mq  [H_ * NB_];
__device__ float g_mk  [H_ * NB_];

// bf16 hi/lo split activation buffers (X = hi + lo, both bf16)
__device__ __align__(128) __nv_bfloat16 g_xh [NTOK * D_];
__device__ __align__(128) __nv_bfloat16 g_xl [NTOK * D_];
__device__ __align__(128) __nv_bfloat16 g_aoh[NTOK * D_];
__device__ __align__(128) __nv_bfloat16 g_aol[NTOK * D_];
__device__ __align__(128) __nv_bfloat16 g_yh [NTOK * D_];
__device__ __align__(128) __nv_bfloat16 g_yl [NTOK * D_];
__device__ __align__(128) __nv_bfloat16 g_hh [NTOK * MLP_];
__device__ __align__(128) __nv_bfloat16 g_hl [NTOK * MLP_];
// bf16 hi/lo split transposed weights [N,K]
__device__ __align__(128) __nv_bfloat16 g_WqTh[D_ * D_],  g_WqTl[D_ * D_];
__device__ __align__(128) __nv_bfloat16 g_WkTh[D_ * D_],  g_WkTl[D_ * D_];
__device__ __align__(128) __nv_bfloat16 g_WvTh[D_ * D_],  g_WvTl[D_ * D_];
__device__ __align__(128) __nv_bfloat16 g_WoTh[D_ * D_],  g_WoTl[D_ * D_];
__device__ __align__(128) __nv_bfloat16 g_W1Th[MLP_ * D_], g_W1Tl[MLP_ * D_];
__device__ __align__(128) __nv_bfloat16 g_W2Th[D_ * MLP_], g_W2Tl[D_ * MLP_];

// ================= PTX helpers (baseline PTX only) =================================
__device__ __forceinline__ uint32_t smem_u32(const void* p) {
    uint32_t a;
    asm("{ .reg .u64 t; cvta.to.shared.u64 t, %1; cvt.u32.u64 %0, t; }" : "=r"(a) : "l"(p));
    return a;
}
__device__ __forceinline__ void cp16(uint32_t dst, const void* src) {
    asm volatile("cp.async.cg.shared.global [%0], [%1], 16;" :: "r"(dst), "l"(src));
}
__device__ __forceinline__ void cp_commit() {
    asm volatile("cp.async.commit_group;" ::: "memory");
}
__device__ __forceinline__ void ldm_x4(uint32_t* r, uint32_t a) {
    asm volatile("ldmatrix.sync.aligned.m8n8.x4.shared.b16 {%0,%1,%2,%3}, [%4];"
        : "=r"(r[0]), "=r"(r[1]), "=r"(r[2]), "=r"(r[3]) : "r"(a));
}
__device__ __forceinline__ void mma16816(float* d, const uint32_t* a, uint32_t b0, uint32_t b1) {
    asm volatile("mma.sync.aligned.m16n8k16.row.col.f32.bf16.bf16.f32 "
        "{%0,%1,%2,%3}, {%4,%5,%6,%7}, {%8,%9}, {%0,%1,%2,%3};"
        : "+f"(d[0]), "+f"(d[1]), "+f"(d[2]), "+f"(d[3])
        : "r"(a[0]), "r"(a[1]), "r"(a[2]), "r"(a[3]), "r"(b0), "r"(b1));
}
__device__ __forceinline__ void split_bf(float v, __nv_bfloat16& hi, __nv_bfloat16& lo) {
    hi = __float2bfloat16(v);
    lo = __float2bfloat16(v - __bfloat162float(hi));
}

// ---------------- zero the loss accumulators ---------------------------------------
__global__ void zero_sums_k() {
    int i = threadIdx.x;
    if (i < H_ * NB_) { g_mq[i] = 0.f; g_mk[i] = 0.f; }
}

// ---------------- weight transpose + bf16 hi/lo split: W[K,N] -> WT[N,K] -----------
__global__ void transpose_bf_k(const float* __restrict__ W,
                               __nv_bfloat16* __restrict__ WTh,
                               __nv_bfloat16* __restrict__ WTl, int K, int N) {
    __shared__ float t[32][33];
    int k0 = blockIdx.x * 32, n0 = blockIdx.y * 32;
    int tx = threadIdx.x, ty = threadIdx.y;   // 32 x 8
#pragma unroll
    for (int i = 0; i < 32; i += 8)
        t[ty + i][tx] = W[(size_t)(k0 + ty + i) * N + n0 + tx];
    __syncthreads();
#pragma unroll
    for (int i = 0; i < 32; i += 8) {
        float v = t[tx][ty + i];
        __nv_bfloat16 hi, lo; split_bf(v, hi, lo);
        size_t o = (size_t)(n0 + ty + i) * K + k0 + tx;
        WTh[o] = hi; WTl[o] = lo;
    }
}

// ---------------- layernorm: bf16 hi/lo output -------------------------------------
__global__ void ln_k(const float* __restrict__ in, const float* __restrict__ g,
                     const float* __restrict__ b,
                     __nv_bfloat16* __restrict__ oh, __nv_bfloat16* __restrict__ ol) {
    int t = blockIdx.x, tid = threadIdx.x;
    const float* x = in + (size_t)t * D_;
    float v[4]; float s = 0.f, s2 = 0.f;
#pragma unroll
    for (int i = 0; i < 4; i++) { v[i] = x[tid + i * 256]; s += v[i]; s2 += v[i] * v[i]; }
#pragma unroll
    for (int o = 16; o; o >>= 1) {
        s  += __shfl_xor_sync(0xffffffffu, s,  o);
        s2 += __shfl_xor_sync(0xffffffffu, s2, o);
    }
    __shared__ float rs[8], rs2[8];
    __shared__ float mu_s, rstd_s;
    int w = tid >> 5, l = tid & 31;
    if (l == 0) { rs[w] = s; rs2[w] = s2; }
    __syncthreads();
    if (tid == 0) {
        float a = 0.f, a2 = 0.f;
        for (int i = 0; i < 8; i++) { a += rs[i]; a2 += rs2[i]; }
        float mu = a * (1.f / D_);
        float var = a2 * (1.f / D_) - mu * mu;
        mu_s = mu; rstd_s = rsqrtf(var + 1e-6f);
    }
    __syncthreads();
    float mu = mu_s, rstd = rstd_s;
#pragma unroll
    for (int i = 0; i < 4; i++) {
        int c = tid + i * 256;
        float vv = (v[i] - mu) * rstd * g[c] + b[c];
        __nv_bfloat16 hi, lo; split_bf(vv, hi, lo);
        oh[(size_t)t * D_ + c] = hi;
        ol[(size_t)t * D_ + c] = lo;
    }
}

// ================= HMMA bf16 split-3 GEMM ==========================================
// C = (Ah+Al) @ (Bh+Bl)^T  ≈  Ah·Bh + Al·Bh + Ah·Bl   (fp32 accum, ~fp32 accuracy)
// 128x128 CTA tile, BK=64 (SW128 smem), 8 warps 4(M)x2(N), cp.async double buffered.
#define GBM 128
#define GBN 128
#define GBK 64

__global__ void __launch_bounds__(256) hgemm_k(
    const __nv_bfloat16* __restrict__ Ah, const __nv_bfloat16* __restrict__ Al,
    const __nv_bfloat16* __restrict__ Bh, const __nv_bfloat16* __restrict__ Bl,
    float* __restrict__ Cf,
    __nv_bfloat16* __restrict__ Cbh, __nv_bfloat16* __restrict__ Cbl,
    int M, int N, int K,
    const float* __restrict__ bias, const float* __restrict__ res, int relu)
{
    extern __shared__ char smem[];
    uint32_t sb = smem_u32(smem);
    uint32_t s0 = (sb + 1023u) & ~1023u;    // 1024-aligned tile base
    int tid = threadIdx.x, wid = tid >> 5, lane = tid & 31;
    int bn = blockIdx.x * GBN, bm = blockIdx.y * GBM;
    int wm = (wid & 3) * 32;                 // warp M offset
    int wn = (wid >> 2) * 64;                // warp N offset

    // buffers: per buf (64KB): Ah@0, Al@16K, Bh@32K, Bl@48K; buf stride 64KB
    auto prefetch = [&](int buf, int k0) {
        uint32_t base = s0 + (uint32_t)buf * 65536u;
#pragma unroll
        for (int i = 0; i < 4; i++) {
            int idx = tid + i * 256;
            int row = idx >> 3; int ch = (idx & 7) * 16;
            uint32_t off = (uint32_t)(row * 128 + ch);
            uint32_t sw = off ^ ((off >> 3) & 0x70u);
            size_t ga = ((size_t)(bm + row) * K + k0) * 2 + ch;
            size_t gb = ((size_t)(bn + row) * K + k0) * 2 + ch;
            cp16(base + sw,           (const char*)Ah + ga);
            cp16(base + 16384u + sw,  (const char*)Al + ga);
            cp16(base + 32768u + sw,  (const char*)Bh + gb);
            cp16(base + 49152u + sw,  (const char*)Bl + gb);
        }
        cp_commit();
    };

    prefetch(0, 0);
    prefetch(1, GBK);

    float acc[2][8][4];
#pragma unroll
    for (int i = 0; i < 2; i++)
#pragma unroll
        for (int j = 0; j < 8; j++)
#pragma unroll
            for (int c = 0; c < 4; c++) acc[i][j][c] = 0.f;

    int NK = K / GBK;
    for (int kt = 0; kt < NK; kt++) {
        int cur = kt & 1;
        if (kt == NK - 1) asm volatile("cp.async.wait_group 0;" ::: "memory");
        else              asm volatile("cp.async.wait_group 1;" ::: "memory");
        __syncthreads();

        uint32_t base = s0 + (uint32_t)cur * 65536u;
#pragma unroll
        for (int ks = 0; ks < 4; ks++) {
            int kb = ks * 32 + ((lane >> 4) << 4);   // byte col for this lane
            uint32_t ah[2][4], al2[2][4];
#pragma unroll
            for (int i = 0; i < 2; i++) {
                uint32_t off = (uint32_t)((wm + i * 16 + (lane & 15)) * 128 + kb);
                uint32_t sw = off ^ ((off >> 3) & 0x70u);
                ldm_x4(ah[i],  base + sw);
                ldm_x4(al2[i], base + 16384u + sw);
            }
            uint32_t bh[4][4], bl2[4][4];
#pragma unroll
            for (int j = 0; j < 4; j++) {
                uint32_t off = (uint32_t)((wn + j * 16 + (lane & 15)) * 128 + kb);
                uint32_t sw = off ^ ((off >> 3) & 0x70u);
                ldm_x4(bh[j],  base + 32768u + sw);
                ldm_x4(bl2[j], base + 49152u + sw);
            }
#pragma unroll
            for (int i = 0; i < 2; i++)
#pragma unroll
                for (int j2 = 0; j2 < 8; j2++) {
                    int jj = j2 >> 1, e = j2 & 1;
                    uint32_t bh0 = bh[jj][e],  bh1 = bh[jj][2 + e];
                    uint32_t bl0 = bl2[jj][e], bl1 = bl2[jj][2 + e];
                    mma16816(acc[i][j2], ah[i],  bh0, bh1);   // Ah*Bh
                    mma16816(acc[i][j2], al2[i], bh0, bh1);   // Al*Bh
                    mma16816(acc[i][j2], ah[i],  bl0, bl1);   // Ah*Bl
                }
        }
        __syncthreads();
        if (kt + 2 < NK) prefetch(cur, (kt + 2) * GBK);
    }

    // epilogue: stage fp32 through smem (aliases tile buffers; tiles dead now)
    float* stg = (float*)(smem + (s0 - sb));
#pragma unroll
    for (int i = 0; i < 2; i++)
#pragma unroll
        for (int j2 = 0; j2 < 8; j2++) {
            int r0 = wm + i * 16 + (lane >> 2);
            int c0 = wn + j2 * 8 + 2 * (lane & 3);
            stg[r0 * 132 + c0]           = acc[i][j2][0];
            stg[r0 * 132 + c0 + 1]       = acc[i][j2][1];
            stg[(r0 + 8) * 132 + c0]     = acc[i][j2][2];
            stg[(r0 + 8) * 132 + c0 + 1] = acc[i][j2][3];
        }
    __syncthreads();

    if (Cbh) {
#pragma unroll
        for (int i = 0; i < 32; i++) {
            int idx = tid + i * 256;
            int rr = idx >> 6, cp = idx & 63;
            int gr = bm + rr, gc = bn + 2 * cp;
            float v0 = stg[rr * 132 + 2 * cp];
            float v1 = stg[rr * 132 + 2 * cp + 1];
            if (bias) { v0 += bias[gc]; v1 += bias[gc + 1]; }
            if (res)  { v0 += res[(size_t)gr * N + gc]; v1 += res[(size_t)gr * N + gc + 1]; }
            if (relu) { v0 = fmaxf(v0, 0.f); v1 = fmaxf(v1, 0.f); }
            __nv_bfloat16 h0, l0, h1, l1;
            split_bf(v0, h0, l0); split_bf(v1, h1, l1);
            __nv_bfloat162 hh; hh.x = h0; hh.y = h1;
            __nv_bfloat162 ll; ll.x = l0; ll.y = l1;
            *(__nv_bfloat162*)&Cbh[(size_t)gr * N + gc] = hh;
            *(__nv_bfloat162*)&Cbl[(size_t)gr * N + gc] = ll;
        }
    } else {
#pragma unroll
        for (int i = 0; i < 64; i++) {
            int idx = tid + i * 256;
            int rr = idx >> 7, cc = idx & 127;
            int gr = bm + rr, gc = bn + cc;
            float v = stg[rr * 132 + cc];
            if (bias) v += bias[gc];
            if (res)  v += res[(size_t)gr * N + gc];
            if (relu) v = fmaxf(v, 0.f);
            Cf[(size_t)gr * N + gc] = v;
        }
    }
}

// ---------------- bucket softmax + extended q'/k' build + loss accumulation --------
__global__ void build_ext_k(const float* __restrict__ Whq, const float* __restrict__ Whk) {
    int wg   = blockIdx.x * 4 + (threadIdx.x >> 5);
    int lane = threadIdx.x & 31;
    int t = wg >> 4, h = wg & 15;
    const float* q = g_q + (size_t)t * D_ + h * DH_;
    const float* k = g_k + (size_t)t * D_ + h * DH_;
    float ql = 0.f, kl = 0.f;
#pragma unroll 8
    for (int f = 0; f < DH_; f++) {
        float qv = q[f], kv = k[f];
        ql += qv * Whq[(h * DH_ + f) * NB_ + lane];
        kl += kv * Whk[(h * DH_ + f) * NB_ + lane];
    }
    float mq = ql, mk = kl;
#pragma unroll
    for (int o = 16; o; o >>= 1) {
        mq = fmaxf(mq, __shfl_xor_sync(0xffffffffu, mq, o));
        mk = fmaxf(mk, __shfl_xor_sync(0xffffffffu, mk, o));
    }
    float eq = __expf(ql - mq), ek = __expf(kl - mk);
    float sq = eq, sk = ek;
#pragma unroll
    for (int o = 16; o; o >>= 1) {
        sq += __shfl_xor_sync(0xffffffffu, sq, o);
        sk += __shfl_xor_sync(0xffffffffu, sk, o);
    }
    float qb = eq / sq, kb = ek / sk;
    float* qe = g_qe + ((size_t)t * H_ + h) * DE_;
    float* ke = g_ke + ((size_t)t * H_ + h) * DE_;
    qe[64 + lane] = 0.1f * qb;
    ke[64 + lane] = kb;
    qe[lane]      = 0.125f * q[lane];
    qe[lane + 32] = 0.125f * q[lane + 32];
    ke[lane]      = k[lane];
    ke[lane + 32] = k[lane + 32];
    atomicAdd(&g_mq[h * NB_ + lane], qb);
    atomicAdd(&g_mk[h * NB_ + lane], kb);
}

// ---------------- flash attention over extended vectors (fp32) ---------------------
__global__ void __launch_bounds__(256) fa_k() {
    extern __shared__ float sm[];
    float* QsT = sm;                        // [DE_][PADE] transposed
    float* KsT = QsT + DE_ * PADE;          // [DE_][PADE]
    float* Vs  = KsT + DE_ * PADE;          // [64][64]
    float* PsT = Vs + 64 * 64;              // [64][65] transposed P

    int tid = threadIdx.x, tx = tid & 15, ty = tid >> 4;
    int blk = blockIdx.x;
    int qt = blk & 31, h = (blk >> 5) & 15, b = blk >> 9;
    int t0 = b * S_ + qt * 64;

#pragma unroll
    for (int i = 0; i < 24; i++) {
        int idx = tid + i * 256; int r = idx / DE_, c = idx - r * DE_;
        QsT[c * PADE + r] = g_qe[((size_t)(t0 + r) * H_ + h) * DE_ + c];
    }
    float o[4][4]; float mrow[4], lrow[4];
#pragma unroll
    for (int i = 0; i < 4; i++) {
        mrow[i] = -1e30f; lrow[i] = 0.f;
#pragma unroll
        for (int j = 0; j < 4; j++) o[i][j] = 0.f;
    }
    __syncthreads();

    for (int kt = 0; kt < S_ / 64; kt++) {
        int k0 = b * S_ + kt * 64;
#pragma unroll
        for (int i = 0; i < 24; i++) {
            int idx = tid + i * 256; int r = idx / DE_, c = idx - r * DE_;
            KsT[c * PADE + r] = g_ke[((size_t)(k0 + r) * H_ + h) * DE_ + c];
        }
#pragma unroll
        for (int i = 0; i < 16; i++) {
            int idx = tid + i * 256; int r = idx >> 6, c = idx & 63;
            Vs[r * 64 + c] = g_v[(size_t)(k0 + r) * D_ + h * DH_ + c];
        }
        __syncthreads();

        float s[4][4];
#pragma unroll
        for (int i = 0; i < 4; i++)
#pragma unroll
            for (int j = 0; j < 4; j++) s[i][j] = 0.f;
#pragma unroll 4
        for (int c = 0; c < DE_; c++) {
            float a[4], bb[4];
            *(float4*)a  = *(const float4*)&QsT[c * PADE + ty * 4];
            *(float4*)bb = *(const float4*)&KsT[c * PADE + tx * 4];
#pragma unroll
            for (int i = 0; i < 4; i++)
#pragma unroll
                for (int j = 0; j < 4; j++) s[i][j] += a[i] * bb[j];
        }

#pragma unroll
        for (int i = 0; i < 4; i++) {
            float mt = fmaxf(fmaxf(s[i][0], s[i][1]), fmaxf(s[i][2], s[i][3]));
#pragma unroll
            for (int off = 8; off; off >>= 1)
                mt = fmaxf(mt, __shfl_xor_sync(0xffffffffu, mt, off));
            float mn  = fmaxf(mrow[i], mt);
            float fac = __expf(mrow[i] - mn);
            float ps = 0.f;
#pragma unroll
            for (int j = 0; j < 4; j++) { s[i][j] = __expf(s[i][j] - mn); ps += s[i][j]; }
#pragma unroll
            for (int off = 8; off; off >>= 1)
                ps += __shfl_xor_sync(0xffffffffu, ps, off);
            lrow[i] = lrow[i] * fac + ps;
            mrow[i] = mn;
#pragma unroll
            for (int j = 0; j < 4; j++) o[i][j] *= fac;
#pragma unroll
            for (int j = 0; j < 4; j++) PsT[(tx * 4 + j) * 65 + ty * 4 + i] = s[i][j];
        }
        __syncthreads();

#pragma unroll 8
        for (int kk = 0; kk < 64; kk++) {
            float a[4], bb[4];
#pragma unroll
            for (int i = 0; i < 4; i++) a[i] = PsT[kk * 65 + ty * 4 + i];
            *(float4*)bb = *(const float4*)&Vs[kk * 64 + tx * 4];
#pragma unroll
            for (int i = 0; i < 4; i++)
#pragma unroll
                for (int j = 0; j < 4; j++) o[i][j] += a[i] * bb[j];
        }
        __syncthreads();
    }

#pragma unroll
    for (int i = 0; i < 4; i++) {
        float inv = 1.f / lrow[i];
#pragma unroll
        for (int j = 0; j < 4; j++) {
            float val = o[i][j] * inv;
            __nv_bfloat16 hi, lo; split_bf(val, hi, lo);
            size_t off = (size_t)(t0 + ty * 4 + i) * D_ + h * DH_ + tx * 4 + j;
            g_aoh[off] = hi; g_aol[off] = lo;
        }
    }
}

// ---------------- auxiliary loss ----------------------------------------------------
__global__ void loss_k(float* out, int do_write) {
    int tid = threadIdx.x;
    float vq = g_mq[tid] * (1.f / NTOK), vk = g_mk[tid] * (1.f / NTOK);
    float s = vq * vq + vk * vk;
#pragma unroll
    for (int off = 16; off; off >>= 1) s += __shfl_xor_sync(0xffffffffu, s, off);
    __shared__ float rs[16];
    if ((tid & 31) == 0) rs[tid >> 5] = s;
    __syncthreads();
    if (tid == 0) {
        float a = 0.f;
        for (int i = 0; i < 16; i++) a += rs[i];
        if (do_write) out[0] = 0.5f * NB_ * (a / H_);
    }
}

// ---------------- launch -----------------------------------------------------------
extern "C" void kernel_launch(void* const* d_in, const int* in_sizes, int n_in,
                              void* d_out, int out_size) {
    const float* inputs = (const float*)d_in[0];
    const float* ln1g   = (const float*)d_in[1];
    const float* ln1b   = (const float*)d_in[2];
    const float* Wq     = (const float*)d_in[3];
    const float* Wk     = (const float*)d_in[4];
    const float* Wv     = (const float*)d_in[5];
    const float* Whq    = (const float*)d_in[6];
    const float* Whk    = (const float*)d_in[7];
    const float* Wo     = (const float*)d_in[8];
    const float* ln2g   = (const float*)d_in[9];
    const float* ln2b   = (const float*)d_in[10];
    const float* W1     = (const float*)d_in[11];
    const float* b1     = (const float*)d_in[12];
    const float* W2     = (const float*)d_in[13];
    const float* b2     = (const float*)d_in[14];
    float* out = (float*)d_out;

    float *q, *k, *v, *xres;
    __nv_bfloat16 *xh, *xl, *aoh, *aol, *yh, *yl, *hh, *hl;
    __nv_bfloat16 *wqh, *wql, *wkh, *wkl, *wvh, *wvl, *woh, *wol, *w1h, *w1l, *w2h, *w2l;
    cudaGetSymbolAddress((void**)&q,    g_q);
    cudaGetSymbolAddress((void**)&k,    g_k);
    cudaGetSymbolAddress((void**)&v,    g_v);
    cudaGetSymbolAddress((void**)&xres, g_xres);
    cudaGetSymbolAddress((void**)&xh,   g_xh);
    cudaGetSymbolAddress((void**)&xl,   g_xl);
    cudaGetSymbolAddress((void**)&aoh,  g_aoh);
    cudaGetSymbolAddress((void**)&aol,  g_aol);
    cudaGetSymbolAddress((void**)&yh,   g_yh);
    cudaGetSymbolAddress((void**)&yl,   g_yl);
    cudaGetSymbolAddress((void**)&hh,   g_hh);
    cudaGetSymbolAddress((void**)&hl,   g_hl);
    cudaGetSymbolAddress((void**)&wqh,  g_WqTh); cudaGetSymbolAddress((void**)&wql, g_WqTl);
    cudaGetSymbolAddress((void**)&wkh,  g_WkTh); cudaGetSymbolAddress((void**)&wkl, g_WkTl);
    cudaGetSymbolAddress((void**)&wvh,  g_WvTh); cudaGetSymbolAddress((void**)&wvl, g_WvTl);
    cudaGetSymbolAddress((void**)&woh,  g_WoTh); cudaGetSymbolAddress((void**)&wol, g_WoTl);
    cudaGetSymbolAddress((void**)&w1h,  g_W1Th); cudaGetSymbolAddress((void**)&w1l, g_W1Tl);
    cudaGetSymbolAddress((void**)&w2h,  g_W2Th); cudaGetSymbolAddress((void**)&w2l, g_W2Tl);

    zero_sums_k<<<1, 512>>>();

    dim3 tb(32, 8);
    transpose_bf_k<<<dim3(D_ / 32, D_ / 32),   tb>>>(Wq, wqh, wql, D_, D_);
    transpose_bf_k<<<dim3(D_ / 32, D_ / 32),   tb>>>(Wk, wkh, wkl, D_, D_);
    transpose_bf_k<<<dim3(D_ / 32, D_ / 32),   tb>>>(Wv, wvh, wvl, D_, D_);
    transpose_bf_k<<<dim3(D_ / 32, D_ / 32),   tb>>>(Wo, woh, wol, D_, D_);
    transpose_bf_k<<<dim3(D_ / 32, MLP_ / 32), tb>>>(W1, w1h, w1l, D_, MLP_);
    transpose_bf_k<<<dim3(MLP_ / 32, D_ / 32), tb>>>(W2, w2h, w2l, MLP_, D_);

    ln_k<<<NTOK, 256>>>(inputs, ln1g, ln1b, xh, xl);

    int gsmem = 1024 + 2 * 65536;          // align pad + 2 x 64KB buffers (stage aliases)
    cudaFuncSetAttribute(hgemm_k, cudaFuncAttributeMaxDynamicSharedMemorySize, gsmem);

    dim3 gqkv(D_ / GBN, NTOK / GBM);       // (8, 32)
    hgemm_k<<<gqkv, 256, gsmem>>>(xh, xl, wqh, wql, q, nullptr, nullptr,
                                  NTOK, D_, D_, nullptr, nullptr, 0);
    hgemm_k<<<gqkv, 256, gsmem>>>(xh, xl, wkh, wkl, k, nullptr, nullptr,
                                  NTOK, D_, D_, nullptr, nullptr, 0);
    hgemm_k<<<gqkv, 256, gsmem>>>(xh, xl, wvh, wvl, v, nullptr, nullptr,
                                  NTOK, D_, D_, nullptr, nullptr, 0);

    build_ext_k<<<NTOK * H_ / 4, 128>>>(Whq, Whk);

    int fasmem = (DE_ * PADE * 2 + 64 * 64 + 64 * 65) * (int)sizeof(float);  // ~85 KB
    cudaFuncSetAttribute(fa_k, cudaFuncAttributeMaxDynamicSharedMemorySize, fasmem);
    fa_k<<<B_ * H_ * (S_ / 64), 256, fasmem>>>();

    // attn @ Wo + residual(inputs) -> xres (fp32)
    hgemm_k<<<gqkv, 256, gsmem>>>(aoh, aol, woh, wol, xres, nullptr, nullptr,
                                  NTOK, D_, D_, nullptr, inputs, 0);

    ln_k<<<NTOK, 256>>>(xres, ln2g, ln2b, yh, yl);

    // MLP1: relu(yln @ W1 + b1) -> bf16 hi/lo h
    dim3 gm1(MLP_ / GBN, NTOK / GBM);      // (32, 32)
    hgemm_k<<<gm1, 256, gsmem>>>(yh, yl, w1h, w1l, nullptr, hh, hl,
                                 NTOK, MLP_, D_, b1, nullptr, 1);
    // MLP2: h @ W2 + b2 + xres -> out (fp32)
    hgemm_k<<<gqkv, 256, gsmem>>>(hh, hl, w2h, w2l, out, nullptr, nullptr,
                                  NTOK, D_, MLP_, b2, xres, 0);

    loss_k<<<1, 512>>>(out + (size_t)NTOK * D_, (out_size > NTOK * D_) ? 1 : 0);
}

// round 12
// speedup vs baseline: 3.5410x; 1.8934x over previous
#include <cuda_runtime.h>
#include <cuda_bf16.h>
#include <math.h>
#include <stdint.h>

// Problem dims
#define B_    2
#define S_    2048
#define D_    1024
#define H_    16
#define DH_   64
#define NB_   32
#define NTOK  4096          // B_*S_
#define MLP_  4096
#define DE_   96            // extended head dim: 64 (content) + 32 (bucket)

// ---------------- scratch (device globals; no allocations allowed) ----------------
__device__ __align__(128) float g_q   [NTOK * D_];
__device__ __align__(128) float g_k   [NTOK * D_];
__device__ __align__(128) float g_v   [NTOK * D_];
__device__ __align__(128) float g_xres[NTOK * D_];
__device__ float g_mq  [H_ * NB_];
__device__ float g_mk  [H_ * NB_];

// bf16 hi/lo split activation buffers (X = hi + lo, both bf16)
__device__ __align__(128) __nv_bfloat16 g_xh [NTOK * D_];
__device__ __align__(128) __nv_bfloat16 g_xl [NTOK * D_];
__device__ __align__(128) __nv_bfloat16 g_aoh[NTOK * D_];
__device__ __align__(128) __nv_bfloat16 g_aol[NTOK * D_];
__device__ __align__(128) __nv_bfloat16 g_yh [NTOK * D_];
__device__ __align__(128) __nv_bfloat16 g_yl [NTOK * D_];
__device__ __align__(128) __nv_bfloat16 g_hh [NTOK * MLP_];
__device__ __align__(128) __nv_bfloat16 g_hl [NTOK * MLP_];
// bf16 hi/lo split transposed weights [N,K]
__device__ __align__(128) __nv_bfloat16 g_WqTh[D_ * D_],  g_WqTl[D_ * D_];
__device__ __align__(128) __nv_bfloat16 g_WkTh[D_ * D_],  g_WkTl[D_ * D_];
__device__ __align__(128) __nv_bfloat16 g_WvTh[D_ * D_],  g_WvTl[D_ * D_];
__device__ __align__(128) __nv_bfloat16 g_WoTh[D_ * D_],  g_WoTl[D_ * D_];
__device__ __align__(128) __nv_bfloat16 g_W1Th[MLP_ * D_], g_W1Tl[MLP_ * D_];
__device__ __align__(128) __nv_bfloat16 g_W2Th[D_ * MLP_], g_W2Tl[D_ * MLP_];

// bf16 FA operands: extended q'/k' [(b*H+h)*S + s][96], V^T [(b*H+h)][dh][S]
__device__ __align__(128) __nv_bfloat16 g_qeb[NTOK * H_ * DE_];
__device__ __align__(128) __nv_bfloat16 g_keb[NTOK * H_ * DE_];
__device__ __align__(128) __nv_bfloat16 g_vt [B_ * H_ * DH_ * S_];

// ================= PTX helpers (baseline PTX only) =================================
__device__ __forceinline__ uint32_t smem_u32(const void* p) {
    uint32_t a;
    asm("{ .reg .u64 t; cvta.to.shared.u64 t, %1; cvt.u32.u64 %0, t; }" : "=r"(a) : "l"(p));
    return a;
}
__device__ __forceinline__ void cp16(uint32_t dst, const void* src) {
    asm volatile("cp.async.cg.shared.global [%0], [%1], 16;" :: "r"(dst), "l"(src));
}
__device__ __forceinline__ void cp_commit() {
    asm volatile("cp.async.commit_group;" ::: "memory");
}
__device__ __forceinline__ void ldm_x4(uint32_t* r, uint32_t a) {
    asm volatile("ldmatrix.sync.aligned.m8n8.x4.shared.b16 {%0,%1,%2,%3}, [%4];"
        : "=r"(r[0]), "=r"(r[1]), "=r"(r[2]), "=r"(r[3]) : "r"(a));
}
__device__ __forceinline__ void mma16816(float* d, const uint32_t* a, uint32_t b0, uint32_t b1) {
    asm volatile("mma.sync.aligned.m16n8k16.row.col.f32.bf16.bf16.f32 "
        "{%0,%1,%2,%3}, {%4,%5,%6,%7}, {%8,%9}, {%0,%1,%2,%3};"
        : "+f"(d[0]), "+f"(d[1]), "+f"(d[2]), "+f"(d[3])
        : "r"(a[0]), "r"(a[1]), "r"(a[2]), "r"(a[3]), "r"(b0), "r"(b1));
}
__device__ __forceinline__ void split_bf(float v, __nv_bfloat16& hi, __nv_bfloat16& lo) {
    hi = __float2bfloat16(v);
    lo = __float2bfloat16(v - __bfloat162float(hi));
}
__device__ __forceinline__ uint32_t packbf(float a, float b) {
    __nv_bfloat162 t = __floats2bfloat162_rn(a, b);
    return *(uint32_t*)&t;
}
__device__ __forceinline__ uint32_t swz(uint32_t off) { return off ^ ((off >> 3) & 0x70u); }

// ---------------- zero the loss accumulators ---------------------------------------
__global__ void zero_sums_k() {
    int i = threadIdx.x;
    if (i < H_ * NB_) { g_mq[i] = 0.f; g_mk[i] = 0.f; }
}

// ---------------- weight transpose + bf16 hi/lo split: W[K,N] -> WT[N,K] -----------
__global__ void transpose_bf_k(const float* __restrict__ W,
                               __nv_bfloat16* __restrict__ WTh,
                               __nv_bfloat16* __restrict__ WTl, int K, int N) {
    __shared__ float t[32][33];
    int k0 = blockIdx.x * 32, n0 = blockIdx.y * 32;
    int tx = threadIdx.x, ty = threadIdx.y;   // 32 x 8
#pragma unroll
    for (int i = 0; i < 32; i += 8)
        t[ty + i][tx] = W[(size_t)(k0 + ty + i) * N + n0 + tx];
    __syncthreads();
#pragma unroll
    for (int i = 0; i < 32; i += 8) {
        float v = t[tx][ty + i];
        __nv_bfloat16 hi, lo; split_bf(v, hi, lo);
        size_t o = (size_t)(n0 + ty + i) * K + k0 + tx;
        WTh[o] = hi; WTl[o] = lo;
    }
}

// ---------------- V transpose per head: g_v[token][D] -> g_vt[(b,h)][dh][S] bf16 ---
// FIXED: covers ALL 64 dh rows (the old version only wrote dh 0..31 — half of
// V^T stayed zero, which exactly produced the 7.96e-3 rel_err).
// Block: one (b,h) x 32 s-positions. 256 threads as (32,8). Tile t[s:32][dh:64+pad].
__global__ void vt_k() {
    __shared__ float t[32][72];
    int bh = blockIdx.x;               // 0..31
    int s0 = blockIdx.y * 32;
    int b = bh >> 4, h = bh & 15;
    int tx = threadIdx.x, ty = threadIdx.y;  // 32 x 8
    // load 32 s-rows x 64 dh-cols (coalesced over tx = dh)
#pragma unroll
    for (int i = 0; i < 4; i++) {
        int s = ty + i * 8;
        t[s][tx]      = g_v[(size_t)(b * S_ + s0 + s) * D_ + h * DH_ + tx];
        t[s][tx + 32] = g_v[(size_t)(b * S_ + s0 + s) * D_ + h * DH_ + tx + 32];
    }
    __syncthreads();
    // store 64 dh-rows x 32 s-cols (coalesced over tx = s)
#pragma unroll
    for (int i = 0; i < 8; i++) {
        int d = ty + i * 8;            // 0..63
        g_vt[((size_t)bh * DH_ + d) * S_ + s0 + tx] = __float2bfloat16(t[tx][d]);
    }
}

// ---------------- layernorm: bf16 hi/lo output -------------------------------------
__global__ void ln_k(const float* __restrict__ in, const float* __restrict__ g,
                     const float* __restrict__ b,
                     __nv_bfloat16* __restrict__ oh, __nv_bfloat16* __restrict__ ol) {
    int t = blockIdx.x, tid = threadIdx.x;
    const float* x = in + (size_t)t * D_;
    float v[4]; float s = 0.f, s2 = 0.f;
#pragma unroll
    for (int i = 0; i < 4; i++) { v[i] = x[tid + i * 256]; s += v[i]; s2 += v[i] * v[i]; }
#pragma unroll
    for (int o = 16; o; o >>= 1) {
        s  += __shfl_xor_sync(0xffffffffu, s,  o);
        s2 += __shfl_xor_sync(0xffffffffu, s2, o);
    }
    __shared__ float rs[8], rs2[8];
    __shared__ float mu_s, rstd_s;
    int w = tid >> 5, l = tid & 31;
    if (l == 0) { rs[w] = s; rs2[w] = s2; }
    __syncthreads();
    if (tid == 0) {
        float a = 0.f, a2 = 0.f;
        for (int i = 0; i < 8; i++) { a += rs[i]; a2 += rs2[i]; }
        float mu = a * (1.f / D_);
        float var = a2 * (1.f / D_) - mu * mu;
        mu_s = mu; rstd_s = rsqrtf(var + 1e-6f);
    }
    __syncthreads();
    float mu = mu_s, rstd = rstd_s;
#pragma unroll
    for (int i = 0; i < 4; i++) {
        int c = tid + i * 256;
        float vv = (v[i] - mu) * rstd * g[c] + b[c];
        __nv_bfloat16 hi, lo; split_bf(vv, hi, lo);
        oh[(size_t)t * D_ + c] = hi;
        ol[(size_t)t * D_ + c] = lo;
    }
}

// ================= HMMA bf16 split-3 GEMM ==========================================
#define GBM 128
#define GBN 128
#define GBK 64

__global__ void __launch_bounds__(256) hgemm_k(
    const __nv_bfloat16* __restrict__ Ah, const __nv_bfloat16* __restrict__ Al,
    const __nv_bfloat16* __restrict__ Bh, const __nv_bfloat16* __restrict__ Bl,
    float* __restrict__ Cf,
    __nv_bfloat16* __restrict__ Cbh, __nv_bfloat16* __restrict__ Cbl,
    int M, int N, int K,
    const float* __restrict__ bias, const float* __restrict__ res, int relu)
{
    extern __shared__ char smem[];
    uint32_t sb = smem_u32(smem);
    uint32_t s0 = (sb + 1023u) & ~1023u;
    int tid = threadIdx.x, wid = tid >> 5, lane = tid & 31;
    int bn = blockIdx.x * GBN, bm = blockIdx.y * GBM;
    int wm = (wid & 3) * 32;
    int wn = (wid >> 2) * 64;

    auto prefetch = [&](int buf, int k0) {
        uint32_t base = s0 + (uint32_t)buf * 65536u;
#pragma unroll
        for (int i = 0; i < 4; i++) {
            int idx = tid + i * 256;
            int row = idx >> 3; int ch = (idx & 7) * 16;
            uint32_t sw = swz((uint32_t)(row * 128 + ch));
            size_t ga = ((size_t)(bm + row) * K + k0) * 2 + ch;
            size_t gb = ((size_t)(bn + row) * K + k0) * 2 + ch;
            cp16(base + sw,           (const char*)Ah + ga);
            cp16(base + 16384u + sw,  (const char*)Al + ga);
            cp16(base + 32768u + sw,  (const char*)Bh + gb);
            cp16(base + 49152u + sw,  (const char*)Bl + gb);
        }
        cp_commit();
    };

    prefetch(0, 0);
    prefetch(1, GBK);

    float acc[2][8][4];
#pragma unroll
    for (int i = 0; i < 2; i++)
#pragma unroll
        for (int j = 0; j < 8; j++)
#pragma unroll
            for (int c = 0; c < 4; c++) acc[i][j][c] = 0.f;

    int NK = K / GBK;
    for (int kt = 0; kt < NK; kt++) {
        int cur = kt & 1;
        if (kt == NK - 1) asm volatile("cp.async.wait_group 0;" ::: "memory");
        else              asm volatile("cp.async.wait_group 1;" ::: "memory");
        __syncthreads();

        uint32_t base = s0 + (uint32_t)cur * 65536u;
#pragma unroll
        for (int ks = 0; ks < 4; ks++) {
            int kb = ks * 32 + ((lane >> 4) << 4);
            uint32_t ah[2][4], al2[2][4];
#pragma unroll
            for (int i = 0; i < 2; i++) {
                uint32_t sw = swz((uint32_t)((wm + i * 16 + (lane & 15)) * 128 + kb));
                ldm_x4(ah[i],  base + sw);
                ldm_x4(al2[i], base + 16384u + sw);
            }
            uint32_t bh[4][4], bl2[4][4];
#pragma unroll
            for (int j = 0; j < 4; j++) {
                uint32_t sw = swz((uint32_t)((wn + j * 16 + (lane & 15)) * 128 + kb));
                ldm_x4(bh[j],  base + 32768u + sw);
                ldm_x4(bl2[j], base + 49152u + sw);
            }
#pragma unroll
            for (int i = 0; i < 2; i++)
#pragma unroll
                for (int j2 = 0; j2 < 8; j2++) {
                    int jj = j2 >> 1, e = j2 & 1;
                    uint32_t bh0 = bh[jj][e],  bh1 = bh[jj][2 + e];
                    uint32_t bl0 = bl2[jj][e], bl1 = bl2[jj][2 + e];
                    mma16816(acc[i][j2], ah[i],  bh0, bh1);
                    mma16816(acc[i][j2], al2[i], bh0, bh1);
                    mma16816(acc[i][j2], ah[i],  bl0, bl1);
                }
        }
        __syncthreads();
        if (kt + 2 < NK) prefetch(cur, (kt + 2) * GBK);
    }

    float* stg = (float*)(smem + (s0 - sb));
#pragma unroll
    for (int i = 0; i < 2; i++)
#pragma unroll
        for (int j2 = 0; j2 < 8; j2++) {
            int r0 = wm + i * 16 + (lane >> 2);
            int c0 = wn + j2 * 8 + 2 * (lane & 3);
            stg[r0 * 132 + c0]           = acc[i][j2][0];
            stg[r0 * 132 + c0 + 1]       = acc[i][j2][1];
            stg[(r0 + 8) * 132 + c0]     = acc[i][j2][2];
            stg[(r0 + 8) * 132 + c0 + 1] = acc[i][j2][3];
        }
    __syncthreads();

    if (Cbh) {
#pragma unroll
        for (int i = 0; i < 32; i++) {
            int idx = tid + i * 256;
            int rr = idx >> 6, cp = idx & 63;
            int gr = bm + rr, gc = bn + 2 * cp;
            float v0 = stg[rr * 132 + 2 * cp];
            float v1 = stg[rr * 132 + 2 * cp + 1];
            if (bias) { v0 += bias[gc]; v1 += bias[gc + 1]; }
            if (res)  { v0 += res[(size_t)gr * N + gc]; v1 += res[(size_t)gr * N + gc + 1]; }
            if (relu) { v0 = fmaxf(v0, 0.f); v1 = fmaxf(v1, 0.f); }
            __nv_bfloat16 h0, l0, h1, l1;
            split_bf(v0, h0, l0); split_bf(v1, h1, l1);
            __nv_bfloat162 hh2; hh2.x = h0; hh2.y = h1;
            __nv_bfloat162 ll2; ll2.x = l0; ll2.y = l1;
            *(__nv_bfloat162*)&Cbh[(size_t)gr * N + gc] = hh2;
            *(__nv_bfloat162*)&Cbl[(size_t)gr * N + gc] = ll2;
        }
    } else {
#pragma unroll
        for (int i = 0; i < 64; i++) {
            int idx = tid + i * 256;
            int rr = idx >> 7, cc = idx & 127;
            int gr = bm + rr, gc = bn + cc;
            float v = stg[rr * 132 + cc];
            if (bias) v += bias[gc];
            if (res)  v += res[(size_t)gr * N + gc];
            if (relu) v = fmaxf(v, 0.f);
            Cf[(size_t)gr * N + gc] = v;
        }
    }
}

// ---------------- bucket softmax + extended q'/k' build (bf16) + loss --------------
__global__ void build_ext_k(const float* __restrict__ Whq, const float* __restrict__ Whk) {
    int wg   = blockIdx.x * 4 + (threadIdx.x >> 5);
    int lane = threadIdx.x & 31;
    int t = wg >> 4, h = wg & 15;
    int b = t >> 11, s = t & 2047;
    const float* q = g_q + (size_t)t * D_ + h * DH_;
    const float* k = g_k + (size_t)t * D_ + h * DH_;
    float ql = 0.f, kl = 0.f;
#pragma unroll 8
    for (int f = 0; f < DH_; f++) {
        float qv = q[f], kv = k[f];
        ql += qv * Whq[(h * DH_ + f) * NB_ + lane];
        kl += kv * Whk[(h * DH_ + f) * NB_ + lane];
    }
    float mq = ql, mk = kl;
#pragma unroll
    for (int o = 16; o; o >>= 1) {
        mq = fmaxf(mq, __shfl_xor_sync(0xffffffffu, mq, o));
        mk = fmaxf(mk, __shfl_xor_sync(0xffffffffu, mk, o));
    }
    float eq = __expf(ql - mq), ek = __expf(kl - mk);
    float sq = eq, sk = ek;
#pragma unroll
    for (int o = 16; o; o >>= 1) {
        sq += __shfl_xor_sync(0xffffffffu, sq, o);
        sk += __shfl_xor_sync(0xffffffffu, sk, o);
    }
    float qb = eq / sq, kb = ek / sk;
    size_t base = ((size_t)(b * H_ + h) * S_ + s) * DE_;
    __nv_bfloat16* qe = g_qeb + base;
    __nv_bfloat16* ke = g_keb + base;
    qe[64 + lane] = __float2bfloat16(0.1f * qb);   // cluster weight folded into q'
    ke[64 + lane] = __float2bfloat16(kb);
    qe[lane]      = __float2bfloat16(0.125f * q[lane]);
    qe[lane + 32] = __float2bfloat16(0.125f * q[lane + 32]);
    ke[lane]      = __float2bfloat16(k[lane]);
    ke[lane + 32] = __float2bfloat16(k[lane + 32]);
    atomicAdd(&g_mq[h * NB_ + lane], qb);
    atomicAdd(&g_mk[h * NB_ + lane], kb);
}

// ================= HMMA flash attention ============================================
// Block: 128 q-rows of one (b,h). 8 warps, each warp m16 x full 64 k-cols.
// Q' frags register-resident (6 k16 steps over 96 dims). K'/V^T double-buffered.
#define FQM 128
__global__ void __launch_bounds__(256) fa_k() {
    extern __shared__ char smem[];
    uint32_t sb = smem_u32(smem);
    uint32_t s0 = (sb + 1023u) & ~1023u;
    uint32_t Q0 = s0, Q1 = s0 + 16384u;            // Q content / bucket subtiles
    uint32_t KV = s0 + 32768u;                     // 2 x 24KB: K0,K1,Vt per buffer
    int tid = threadIdx.x, wid = tid >> 5, lane = tid & 31;
    int blk = blockIdx.x;
    int qt = blk & 15, h = (blk >> 4) & 15, b = blk >> 8;
    int bh = b * H_ + h;
    int t0q = b * S_ + qt * FQM;                   // global token row base

    const char* qsrc = (const char*)(g_qeb + ((size_t)bh * S_ + qt * FQM) * DE_);
    const char* ksrc0 = (const char*)(g_keb + (size_t)bh * S_ * DE_);
    const char* vsrc0 = (const char*)(g_vt + (size_t)bh * DH_ * S_);

    // ---- load Q tile: 128 rows x 12 chunks (16B) ----
#pragma unroll
    for (int i = 0; i < 6; i++) {
        int idx = tid + i * 256;
        int row = idx / 12, c = idx - row * 12;
        uint32_t dst = (c < 8) ? (Q0 + swz((uint32_t)(row * 128 + c * 16)))
                               : (Q1 + swz((uint32_t)(row * 128 + (c - 8) * 16)));
        cp16(dst, qsrc + (size_t)row * (DE_ * 2) + c * 16);
    }
    cp_commit();

    auto prefetch = [&](int buf, int kt) {
        uint32_t base = KV + (uint32_t)buf * 24576u;
        const char* ks = ksrc0 + (size_t)(kt * 64) * (DE_ * 2);
#pragma unroll
        for (int i = 0; i < 3; i++) {               // K': 64 rows x 12 chunks
            int idx = tid + i * 256;
            int row = idx / 12, c = idx - row * 12;
            uint32_t dst = (c < 8) ? (base + swz((uint32_t)(row * 128 + c * 16)))
                                   : (base + 8192u + swz((uint32_t)(row * 128 + (c - 8) * 16)));
            cp16(dst, ks + (size_t)row * (DE_ * 2) + c * 16);
        }
#pragma unroll
        for (int i = 0; i < 2; i++) {               // V^T: 64 rows x 8 chunks
            int idx = tid + i * 256;
            int row = idx >> 3, c = idx & 7;
            cp16(base + 16384u + swz((uint32_t)(row * 128 + c * 16)),
                 vsrc0 + (size_t)row * (S_ * 2) + kt * 128 + c * 16);
        }
        cp_commit();
    };

    prefetch(0, 0);
    asm volatile("cp.async.wait_group 1;" ::: "memory");   // Q done
    __syncthreads();

    // ---- Q' fragments into registers: 6 k16-steps ----
    uint32_t qf[6][4];
#pragma unroll
    for (int ks = 0; ks < 6; ks++) {
        uint32_t base = (ks < 4) ? Q0 : Q1;
        int kb = ((ks < 4) ? ks * 32 : (ks - 4) * 32) + ((lane >> 4) << 4);
        ldm_x4(qf[ks], base + swz((uint32_t)((wid * 16 + (lane & 15)) * 128 + kb)));
    }

    float o[8][4];
#pragma unroll
    for (int j = 0; j < 8; j++)
#pragma unroll
        for (int c = 0; c < 4; c++) o[j][c] = 0.f;
    float mrow[2] = {-1e30f, -1e30f}, lrow[2] = {0.f, 0.f};

    const int NT = S_ / 64;
    for (int kt = 0; kt < NT; kt++) {
        int cur = kt & 1;
        if (kt + 1 < NT) { prefetch(cur ^ 1, kt + 1); asm volatile("cp.async.wait_group 1;" ::: "memory"); }
        else             { asm volatile("cp.async.wait_group 0;" ::: "memory"); }
        __syncthreads();

        uint32_t kbase = KV + (uint32_t)cur * 24576u;

        // S = Q' K'^T : 6 k16-steps, 8 n8 frags
        float s[8][4];
#pragma unroll
        for (int j = 0; j < 8; j++)
#pragma unroll
            for (int c = 0; c < 4; c++) s[j][c] = 0.f;
#pragma unroll
        for (int ks = 0; ks < 6; ks++) {
            uint32_t base = (ks < 4) ? kbase : (kbase + 8192u);
            int kb = ((ks < 4) ? ks * 32 : (ks - 4) * 32) + ((lane >> 4) << 4);
            uint32_t bf[4][4];
#pragma unroll
            for (int j = 0; j < 4; j++)
                ldm_x4(bf[j], base + swz((uint32_t)((j * 16 + (lane & 15)) * 128 + kb)));
#pragma unroll
            for (int j2 = 0; j2 < 8; j2++) {
                int jj = j2 >> 1, e = j2 & 1;
                mma16816(s[j2], qf[ks], bf[jj][e], bf[jj][2 + e]);
            }
        }

        // online softmax per row-half (r0 = lane>>2, r0+8); row spans quad lanes
        float fac[2];
#pragma unroll
        for (int hf = 0; hf < 2; hf++) {
            float mt = -1e30f;
#pragma unroll
            for (int j = 0; j < 8; j++)
                mt = fmaxf(mt, fmaxf(s[j][2 * hf], s[j][2 * hf + 1]));
            mt = fmaxf(mt, __shfl_xor_sync(0xffffffffu, mt, 1));
            mt = fmaxf(mt, __shfl_xor_sync(0xffffffffu, mt, 2));
            float mn = fmaxf(mrow[hf], mt);
            fac[hf] = __expf(mrow[hf] - mn);
            float ps = 0.f;
#pragma unroll
            for (int j = 0; j < 8; j++) {
                float p0 = __expf(s[j][2 * hf]     - mn);
                float p1 = __expf(s[j][2 * hf + 1] - mn);
                s[j][2 * hf] = p0; s[j][2 * hf + 1] = p1;
                ps += p0 + p1;
            }
            ps += __shfl_xor_sync(0xffffffffu, ps, 1);
            ps += __shfl_xor_sync(0xffffffffu, ps, 2);
            lrow[hf] = lrow[hf] * fac[hf] + ps;
            mrow[hf] = mn;
        }
#pragma unroll
        for (int j = 0; j < 8; j++) {
            o[j][0] *= fac[0]; o[j][1] *= fac[0];
            o[j][2] *= fac[1]; o[j][3] *= fac[1];
        }

        // P frags (A-layout) straight from S accum frags:
        // chunk kb2 covers key positions [16*kb2, 16*kb2+16):
        //   a0 = P(row, klow)  = pack(s[2kb2][0], s[2kb2][1])
        //   a1 = P(row+8, klow)= pack(s[2kb2][2], s[2kb2][3])
        //   a2 = P(row, khigh) = pack(s[2kb2+1][0], s[2kb2+1][1])
        //   a3 = P(row+8,khigh)= pack(s[2kb2+1][2], s[2kb2+1][3])
        uint32_t pf[4][4];
#pragma unroll
        for (int kb2 = 0; kb2 < 4; kb2++) {
            pf[kb2][0] = packbf(s[2 * kb2][0],     s[2 * kb2][1]);
            pf[kb2][1] = packbf(s[2 * kb2][2],     s[2 * kb2][3]);
            pf[kb2][2] = packbf(s[2 * kb2 + 1][0], s[2 * kb2 + 1][1]);
            pf[kb2][3] = packbf(s[2 * kb2 + 1][2], s[2 * kb2 + 1][3]);
        }

        // O += P V : V^T tile [dh=64 rows][kpos=64 cols], 4 k16-steps
        uint32_t vbase = kbase + 16384u;
#pragma unroll
        for (int kb2 = 0; kb2 < 4; kb2++) {
            int kb = kb2 * 32 + ((lane >> 4) << 4);
            uint32_t bf[4][4];
#pragma unroll
            for (int j = 0; j < 4; j++)
                ldm_x4(bf[j], vbase + swz((uint32_t)((j * 16 + (lane & 15)) * 128 + kb)));
#pragma unroll
            for (int j2 = 0; j2 < 8; j2++) {
                int jj = j2 >> 1, e = j2 & 1;
                mma16816(o[j2], pf[kb2], bf[jj][e], bf[jj][2 + e]);
            }
        }
        __syncthreads();   // all warps done with buffer before next prefetch overwrites
    }

    // ---- write O (bf16 hi/lo for the Wo split-3 GEMM) ----
    float inv0 = 1.f / lrow[0], inv1 = 1.f / lrow[1];
#pragma unroll
    for (int j2 = 0; j2 < 8; j2++) {
        int col = h * DH_ + j2 * 8 + 2 * (lane & 3);
#pragma unroll
        for (int hf = 0; hf < 2; hf++) {
            int row = t0q + wid * 16 + (lane >> 2) + hf * 8;
            float iv = hf ? inv1 : inv0;
            float v0 = o[j2][2 * hf] * iv, v1 = o[j2][2 * hf + 1] * iv;
            __nv_bfloat16 h0, l0, h1, l1;
            split_bf(v0, h0, l0); split_bf(v1, h1, l1);
            __nv_bfloat162 hh2; hh2.x = h0; hh2.y = h1;
            __nv_bfloat162 ll2; ll2.x = l0; ll2.y = l1;
            *(__nv_bfloat162*)&g_aoh[(size_t)row * D_ + col] = hh2;
            *(__nv_bfloat162*)&g_aol[(size_t)row * D_ + col] = ll2;
        }
    }
}

// ---------------- auxiliary loss ----------------------------------------------------
__global__ void loss_k(float* out, int do_write) {
    int tid = threadIdx.x;
    float vq = g_mq[tid] * (1.f / NTOK), vk = g_mk[tid] * (1.f / NTOK);
    float s = vq * vq + vk * vk;
#pragma unroll
    for (int off = 16; off; off >>= 1) s += __shfl_xor_sync(0xffffffffu, s, off);
    __shared__ float rs[16];
    if ((tid & 31) == 0) rs[tid >> 5] = s;
    __syncthreads();
    if (tid == 0) {
        float a = 0.f;
        for (int i = 0; i < 16; i++) a += rs[i];
        if (do_write) out[0] = 0.5f * NB_ * (a / H_);
    }
}

// ---------------- launch -----------------------------------------------------------
extern "C" void kernel_launch(void* const* d_in, const int* in_sizes, int n_in,
                              void* d_out, int out_size) {
    const float* inputs = (const float*)d_in[0];
    const float* ln1g   = (const float*)d_in[1];
    const float* ln1b   = (const float*)d_in[2];
    const float* Wq     = (const float*)d_in[3];
    const float* Wk     = (const float*)d_in[4];
    const float* Wv     = (const float*)d_in[5];
    const float* Whq    = (const float*)d_in[6];
    const float* Whk    = (const float*)d_in[7];
    const float* Wo     = (const float*)d_in[8];
    const float* ln2g   = (const float*)d_in[9];
    const float* ln2b   = (const float*)d_in[10];
    const float* W1     = (const float*)d_in[11];
    const float* b1     = (const float*)d_in[12];
    const float* W2     = (const float*)d_in[13];
    const float* b2     = (const float*)d_in[14];
    float* out = (float*)d_out;

    float *q, *k, *v, *xres;
    __nv_bfloat16 *xh, *xl, *aoh, *aol, *yh, *yl, *hh, *hl;
    __nv_bfloat16 *wqh, *wql, *wkh, *wkl, *wvh, *wvl, *woh, *wol, *w1h, *w1l, *w2h, *w2l;
    cudaGetSymbolAddress((void**)&q,    g_q);
    cudaGetSymbolAddress((void**)&k,    g_k);
    cudaGetSymbolAddress((void**)&v,    g_v);
    cudaGetSymbolAddress((void**)&xres, g_xres);
    cudaGetSymbolAddress((void**)&xh,   g_xh);
    cudaGetSymbolAddress((void**)&xl,   g_xl);
    cudaGetSymbolAddress((void**)&aoh,  g_aoh);
    cudaGetSymbolAddress((void**)&aol,  g_aol);
    cudaGetSymbolAddress((void**)&yh,   g_yh);
    cudaGetSymbolAddress((void**)&yl,   g_yl);
    cudaGetSymbolAddress((void**)&hh,   g_hh);
    cudaGetSymbolAddress((void**)&hl,   g_hl);
    cudaGetSymbolAddress((void**)&wqh,  g_WqTh); cudaGetSymbolAddress((void**)&wql, g_WqTl);
    cudaGetSymbolAddress((void**)&wkh,  g_WkTh); cudaGetSymbolAddress((void**)&wkl, g_WkTl);
    cudaGetSymbolAddress((void**)&wvh,  g_WvTh); cudaGetSymbolAddress((void**)&wvl, g_WvTl);
    cudaGetSymbolAddress((void**)&woh,  g_WoTh); cudaGetSymbolAddress((void**)&wol, g_WoTl);
    cudaGetSymbolAddress((void**)&w1h,  g_W1Th); cudaGetSymbolAddress((void**)&w1l, g_W1Tl);
    cudaGetSymbolAddress((void**)&w2h,  g_W2Th); cudaGetSymbolAddress((void**)&w2l, g_W2Tl);

    zero_sums_k<<<1, 512>>>();

    dim3 tb(32, 8);
    transpose_bf_k<<<dim3(D_ / 32, D_ / 32),   tb>>>(Wq, wqh, wql, D_, D_);
    transpose_bf_k<<<dim3(D_ / 32, D_ / 32),   tb>>>(Wk, wkh, wkl, D_, D_);
    transpose_bf_k<<<dim3(D_ / 32, D_ / 32),   tb>>>(Wv, wvh, wvl, D_, D_);
    transpose_bf_k<<<dim3(D_ / 32, D_ / 32),   tb>>>(Wo, woh, wol, D_, D_);
    transpose_bf_k<<<dim3(D_ / 32, MLP_ / 32), tb>>>(W1, w1h, w1l, D_, MLP_);
    transpose_bf_k<<<dim3(MLP_ / 32, D_ / 32), tb>>>(W2, w2h, w2l, MLP_, D_);

    ln_k<<<NTOK, 256>>>(inputs, ln1g, ln1b, xh, xl);

    int gsmem = 1024 + 2 * 65536;
    cudaFuncSetAttribute(hgemm_k, cudaFuncAttributeMaxDynamicSharedMemorySize, gsmem);

    dim3 gqkv(D_ / GBN, NTOK / GBM);       // (8, 32)
    hgemm_k<<<gqkv, 256, gsmem>>>(xh, xl, wqh, wql, q, nullptr, nullptr,
                                  NTOK, D_, D_, nullptr, nullptr, 0);
    hgemm_k<<<gqkv, 256, gsmem>>>(xh, xl, wkh, wkl, k, nullptr, nullptr,
                                  NTOK, D_, D_, nullptr, nullptr, 0);
    hgemm_k<<<gqkv, 256, gsmem>>>(xh, xl, wvh, wvl, v, nullptr, nullptr,
                                  NTOK, D_, D_, nullptr, nullptr, 0);

    build_ext_k<<<NTOK * H_ / 4, 128>>>(Whq, Whk);
    vt_k<<<dim3(B_ * H_, S_ / 32), tb>>>();

    int fasmem = 1024 + 32768 + 2 * 24576;   // ~82 KB
    cudaFuncSetAttribute(fa_k, cudaFuncAttributeMaxDynamicSharedMemorySize, fasmem);
    fa_k<<<B_ * H_ * (S_ / FQM), 256, fasmem>>>();

    hgemm_k<<<gqkv, 256, gsmem>>>(aoh, aol, woh, wol, xres, nullptr, nullptr,
                                  NTOK, D_, D_, nullptr, inputs, 0);

    ln_k<<<NTOK, 256>>>(xres, ln2g, ln2b, yh, yl);

    dim3 gm1(MLP_ / GBN, NTOK / GBM);      // (32, 32)
    hgemm_k<<<gm1, 256, gsmem>>>(yh, yl, w1h, w1l, nullptr, hh, hl,
                                 NTOK, MLP_, D_, b1, nullptr, 1);
    hgemm_k<<<gqkv, 256, gsmem>>>(hh, hl, w2h, w2l, out, nullptr, nullptr,
                                  NTOK, D_, MLP_, b2, xres, 0);

    loss_k<<<1, 512>>>(out + (size_t)NTOK * D_, (out_size > NTOK * D_) ? 1 : 0);
}

// round 13
// speedup vs baseline: 4.2540x; 1.2013x over previous
#include <cuda_runtime.h>
#include <cuda_bf16.h>
#include <math.h>
#include <stdint.h>

// Problem dims
#define B_    2
#define S_    2048
#define D_    1024
#define H_    16
#define DH_   64
#define NB_   32
#define NTOK  4096          // B_*S_
#define MLP_  4096
#define DE_   96            // extended head dim: 64 (content) + 32 (bucket)

// ---------------- scratch (device globals; no allocations allowed) ----------------
__device__ __align__(128) float g_q   [NTOK * D_];
__device__ __align__(128) float g_k   [NTOK * D_];
__device__ __align__(128) float g_v   [NTOK * D_];
__device__ __align__(128) float g_xres[NTOK * D_];
__device__ float g_mq  [H_ * NB_];
__device__ float g_mk  [H_ * NB_];

// bf16 activation buffers
__device__ __align__(128) __nv_bfloat16 g_xh [NTOK * D_];     // ln1 out (plain bf16)
__device__ __align__(128) __nv_bfloat16 g_aoh[NTOK * D_];     // attn out (plain bf16)
__device__ __align__(128) __nv_bfloat16 g_yh [NTOK * D_];     // ln2 out hi
__device__ __align__(128) __nv_bfloat16 g_yl [NTOK * D_];     // ln2 out lo
__device__ __align__(128) __nv_bfloat16 g_hh [NTOK * MLP_];   // mlp hidden hi
__device__ __align__(128) __nv_bfloat16 g_hl [NTOK * MLP_];   // mlp hidden lo
// transposed weights [N,K]: QKV/Wo plain bf16; W1/W2 hi/lo split
__device__ __align__(128) __nv_bfloat16 g_WqT[D_ * D_];
__device__ __align__(128) __nv_bfloat16 g_WkT[D_ * D_];
__device__ __align__(128) __nv_bfloat16 g_WvT[D_ * D_];
__device__ __align__(128) __nv_bfloat16 g_WoT[D_ * D_];
__device__ __align__(128) __nv_bfloat16 g_W1Th[MLP_ * D_], g_W1Tl[MLP_ * D_];
__device__ __align__(128) __nv_bfloat16 g_W2Th[D_ * MLP_], g_W2Tl[D_ * MLP_];

// bf16 FA operands: extended q'/k' [(b*H+h)*S + s][96], V^T [(b*H+h)][dh][S]
__device__ __align__(128) __nv_bfloat16 g_qeb[NTOK * H_ * DE_];
__device__ __align__(128) __nv_bfloat16 g_keb[NTOK * H_ * DE_];
__device__ __align__(128) __nv_bfloat16 g_vt [B_ * H_ * DH_ * S_];

// ================= PTX helpers (baseline PTX only) =================================
__device__ __forceinline__ uint32_t smem_u32(const void* p) {
    uint32_t a;
    asm("{ .reg .u64 t; cvta.to.shared.u64 t, %1; cvt.u32.u64 %0, t; }" : "=r"(a) : "l"(p));
    return a;
}
__device__ __forceinline__ void cp16(uint32_t dst, const void* src) {
    asm volatile("cp.async.cg.shared.global [%0], [%1], 16;" :: "r"(dst), "l"(src));
}
__device__ __forceinline__ void cp_commit() {
    asm volatile("cp.async.commit_group;" ::: "memory");
}
__device__ __forceinline__ void ldm_x4(uint32_t* r, uint32_t a) {
    asm volatile("ldmatrix.sync.aligned.m8n8.x4.shared.b16 {%0,%1,%2,%3}, [%4];"
        : "=r"(r[0]), "=r"(r[1]), "=r"(r[2]), "=r"(r[3]) : "r"(a));
}
__device__ __forceinline__ void mma16816(float* d, const uint32_t* a, uint32_t b0, uint32_t b1) {
    asm volatile("mma.sync.aligned.m16n8k16.row.col.f32.bf16.bf16.f32 "
        "{%0,%1,%2,%3}, {%4,%5,%6,%7}, {%8,%9}, {%0,%1,%2,%3};"
        : "+f"(d[0]), "+f"(d[1]), "+f"(d[2]), "+f"(d[3])
        : "r"(a[0]), "r"(a[1]), "r"(a[2]), "r"(a[3]), "r"(b0), "r"(b1));
}
__device__ __forceinline__ void split_bf(float v, __nv_bfloat16& hi, __nv_bfloat16& lo) {
    hi = __float2bfloat16(v);
    lo = __float2bfloat16(v - __bfloat162float(hi));
}
__device__ __forceinline__ uint32_t packbf(float a, float b) {
    __nv_bfloat162 t = __floats2bfloat162_rn(a, b);
    return *(uint32_t*)&t;
}
__device__ __forceinline__ uint32_t swz(uint32_t off) { return off ^ ((off >> 3) & 0x70u); }

// ---------------- zero the loss accumulators ---------------------------------------
__global__ void zero_sums_k() {
    int i = threadIdx.x;
    if (i < H_ * NB_) { g_mq[i] = 0.f; g_mk[i] = 0.f; }
}

// ---------------- weight transpose + bf16 (optional hi/lo): W[K,N] -> WT[N,K] ------
__global__ void transpose_bf_k(const float* __restrict__ W,
                               __nv_bfloat16* __restrict__ WTh,
                               __nv_bfloat16* __restrict__ WTl, int K, int N) {
    __shared__ float t[32][33];
    int k0 = blockIdx.x * 32, n0 = blockIdx.y * 32;
    int tx = threadIdx.x, ty = threadIdx.y;   // 32 x 8
#pragma unroll
    for (int i = 0; i < 32; i += 8)
        t[ty + i][tx] = W[(size_t)(k0 + ty + i) * N + n0 + tx];
    __syncthreads();
#pragma unroll
    for (int i = 0; i < 32; i += 8) {
        float v = t[tx][ty + i];
        size_t o = (size_t)(n0 + ty + i) * K + k0 + tx;
        if (WTl) {
            __nv_bfloat16 hi, lo; split_bf(v, hi, lo);
            WTh[o] = hi; WTl[o] = lo;
        } else {
            WTh[o] = __float2bfloat16(v);
        }
    }
}

// ---------------- V transpose per head: g_v[token][D] -> g_vt[(b,h)][dh][S] bf16 ---
__global__ void vt_k() {
    __shared__ float t[32][72];
    int bh = blockIdx.x;               // 0..31
    int s0 = blockIdx.y * 32;
    int b = bh >> 4, h = bh & 15;
    int tx = threadIdx.x, ty = threadIdx.y;  // 32 x 8
#pragma unroll
    for (int i = 0; i < 4; i++) {
        int s = ty + i * 8;
        t[s][tx]      = g_v[(size_t)(b * S_ + s0 + s) * D_ + h * DH_ + tx];
        t[s][tx + 32] = g_v[(size_t)(b * S_ + s0 + s) * D_ + h * DH_ + tx + 32];
    }
    __syncthreads();
#pragma unroll
    for (int i = 0; i < 8; i++) {
        int d = ty + i * 8;            // 0..63
        g_vt[((size_t)bh * DH_ + d) * S_ + s0 + tx] = __float2bfloat16(t[tx][d]);
    }
}

// ---------------- layernorm: bf16 out (optional lo) --------------------------------
__global__ void ln_k(const float* __restrict__ in, const float* __restrict__ g,
                     const float* __restrict__ b,
                     __nv_bfloat16* __restrict__ oh, __nv_bfloat16* __restrict__ ol) {
    int t = blockIdx.x, tid = threadIdx.x;
    const float* x = in + (size_t)t * D_;
    float v[4]; float s = 0.f, s2 = 0.f;
#pragma unroll
    for (int i = 0; i < 4; i++) { v[i] = x[tid + i * 256]; s += v[i]; s2 += v[i] * v[i]; }
#pragma unroll
    for (int o = 16; o; o >>= 1) {
        s  += __shfl_xor_sync(0xffffffffu, s,  o);
        s2 += __shfl_xor_sync(0xffffffffu, s2, o);
    }
    __shared__ float rs[8], rs2[8];
    __shared__ float mu_s, rstd_s;
    int w = tid >> 5, l = tid & 31;
    if (l == 0) { rs[w] = s; rs2[w] = s2; }
    __syncthreads();
    if (tid == 0) {
        float a = 0.f, a2 = 0.f;
        for (int i = 0; i < 8; i++) { a += rs[i]; a2 += rs2[i]; }
        float mu = a * (1.f / D_);
        float var = a2 * (1.f / D_) - mu * mu;
        mu_s = mu; rstd_s = rsqrtf(var + 1e-6f);
    }
    __syncthreads();
    float mu = mu_s, rstd = rstd_s;
#pragma unroll
    for (int i = 0; i < 4; i++) {
        int c = tid + i * 256;
        float vv = (v[i] - mu) * rstd * g[c] + b[c];
        if (ol) {
            __nv_bfloat16 hi, lo; split_bf(vv, hi, lo);
            oh[(size_t)t * D_ + c] = hi;
            ol[(size_t)t * D_ + c] = lo;
        } else {
            oh[(size_t)t * D_ + c] = __float2bfloat16(vv);
        }
    }
}

// ================= HMMA bf16 split-3 GEMM (MLP path, ~fp32 accuracy) ===============
#define GBM 128
#define GBN 128
#define GBK 64

__global__ void __launch_bounds__(256) hgemm_k(
    const __nv_bfloat16* __restrict__ Ah, const __nv_bfloat16* __restrict__ Al,
    const __nv_bfloat16* __restrict__ Bh, const __nv_bfloat16* __restrict__ Bl,
    float* __restrict__ Cf,
    __nv_bfloat16* __restrict__ Cbh, __nv_bfloat16* __restrict__ Cbl,
    int M, int N, int K,
    const float* __restrict__ bias, const float* __restrict__ res, int relu)
{
    extern __shared__ char smem[];
    uint32_t sb = smem_u32(smem);
    uint32_t s0 = (sb + 1023u) & ~1023u;
    int tid = threadIdx.x, wid = tid >> 5, lane = tid & 31;
    int bn = blockIdx.x * GBN, bm = blockIdx.y * GBM;
    int wm = (wid & 3) * 32;
    int wn = (wid >> 2) * 64;

    auto prefetch = [&](int buf, int k0) {
        uint32_t base = s0 + (uint32_t)buf * 65536u;
#pragma unroll
        for (int i = 0; i < 4; i++) {
            int idx = tid + i * 256;
            int row = idx >> 3; int ch = (idx & 7) * 16;
            uint32_t sw = swz((uint32_t)(row * 128 + ch));
            size_t ga = ((size_t)(bm + row) * K + k0) * 2 + ch;
            size_t gb = ((size_t)(bn + row) * K + k0) * 2 + ch;
            cp16(base + sw,           (const char*)Ah + ga);
            cp16(base + 16384u + sw,  (const char*)Al + ga);
            cp16(base + 32768u + sw,  (const char*)Bh + gb);
            cp16(base + 49152u + sw,  (const char*)Bl + gb);
        }
        cp_commit();
    };

    prefetch(0, 0);
    prefetch(1, GBK);

    float acc[2][8][4];
#pragma unroll
    for (int i = 0; i < 2; i++)
#pragma unroll
        for (int j = 0; j < 8; j++)
#pragma unroll
            for (int c = 0; c < 4; c++) acc[i][j][c] = 0.f;

    int NK = K / GBK;
    for (int kt = 0; kt < NK; kt++) {
        int cur = kt & 1;
        if (kt == NK - 1) asm volatile("cp.async.wait_group 0;" ::: "memory");
        else              asm volatile("cp.async.wait_group 1;" ::: "memory");
        __syncthreads();

        uint32_t base = s0 + (uint32_t)cur * 65536u;
#pragma unroll
        for (int ks = 0; ks < 4; ks++) {
            int kb = ks * 32 + ((lane >> 4) << 4);
            uint32_t ah[2][4], al2[2][4];
#pragma unroll
            for (int i = 0; i < 2; i++) {
                uint32_t sw = swz((uint32_t)((wm + i * 16 + (lane & 15)) * 128 + kb));
                ldm_x4(ah[i],  base + sw);
                ldm_x4(al2[i], base + 16384u + sw);
            }
            uint32_t bh[4][4], bl2[4][4];
#pragma unroll
            for (int j = 0; j < 4; j++) {
                uint32_t sw = swz((uint32_t)((wn + j * 16 + (lane & 15)) * 128 + kb));
                ldm_x4(bh[j],  base + 32768u + sw);
                ldm_x4(bl2[j], base + 49152u + sw);
            }
#pragma unroll
            for (int i = 0; i < 2; i++)
#pragma unroll
                for (int j2 = 0; j2 < 8; j2++) {
                    int jj = j2 >> 1, e = j2 & 1;
                    uint32_t bh0 = bh[jj][e],  bh1 = bh[jj][2 + e];
                    uint32_t bl0 = bl2[jj][e], bl1 = bl2[jj][2 + e];
                    mma16816(acc[i][j2], ah[i],  bh0, bh1);
                    mma16816(acc[i][j2], al2[i], bh0, bh1);
                    mma16816(acc[i][j2], ah[i],  bl0, bl1);
                }
        }
        __syncthreads();
        if (kt + 2 < NK) prefetch(cur, (kt + 2) * GBK);
    }

    float* stg = (float*)(smem + (s0 - sb));
#pragma unroll
    for (int i = 0; i < 2; i++)
#pragma unroll
        for (int j2 = 0; j2 < 8; j2++) {
            int r0 = wm + i * 16 + (lane >> 2);
            int c0 = wn + j2 * 8 + 2 * (lane & 3);
            stg[r0 * 132 + c0]           = acc[i][j2][0];
            stg[r0 * 132 + c0 + 1]       = acc[i][j2][1];
            stg[(r0 + 8) * 132 + c0]     = acc[i][j2][2];
            stg[(r0 + 8) * 132 + c0 + 1] = acc[i][j2][3];
        }
    __syncthreads();

    if (Cbh) {
#pragma unroll
        for (int i = 0; i < 32; i++) {
            int idx = tid + i * 256;
            int rr = idx >> 6, cp = idx & 63;
            int gr = bm + rr, gc = bn + 2 * cp;
            float v0 = stg[rr * 132 + 2 * cp];
            float v1 = stg[rr * 132 + 2 * cp + 1];
            if (bias) { v0 += bias[gc]; v1 += bias[gc + 1]; }
            if (res)  { v0 += res[(size_t)gr * N + gc]; v1 += res[(size_t)gr * N + gc + 1]; }
            if (relu) { v0 = fmaxf(v0, 0.f); v1 = fmaxf(v1, 0.f); }
            __nv_bfloat16 h0, l0, h1, l1;
            split_bf(v0, h0, l0); split_bf(v1, h1, l1);
            __nv_bfloat162 hh2; hh2.x = h0; hh2.y = h1;
            __nv_bfloat162 ll2; ll2.x = l0; ll2.y = l1;
            *(__nv_bfloat162*)&Cbh[(size_t)gr * N + gc] = hh2;
            *(__nv_bfloat162*)&Cbl[(size_t)gr * N + gc] = ll2;
        }
    } else {
#pragma unroll
        for (int i = 0; i < 64; i++) {
            int idx = tid + i * 256;
            int rr = idx >> 7, cc = idx & 127;
            int gr = bm + rr, gc = bn + cc;
            float v = stg[rr * 132 + cc];
            if (bias) v += bias[gc];
            if (res)  v += res[(size_t)gr * N + gc];
            if (relu) v = fmaxf(v, 0.f);
            Cf[(size_t)gr * N + gc] = v;
        }
    }
}

// ================= HMMA bf16 plain GEMM (QKV / Wo path) ============================
// Same tiling, single MMA per product term, 32KB/buffer -> 2 CTAs/SM.
__global__ void __launch_bounds__(256) hgemm_p_k(
    const __nv_bfloat16* __restrict__ Ah, const __nv_bfloat16* __restrict__ Bh,
    float* __restrict__ Cf, int M, int N, int K,
    const float* __restrict__ res)
{
    extern __shared__ char smem[];
    uint32_t sb = smem_u32(smem);
    uint32_t s0 = (sb + 1023u) & ~1023u;
    int tid = threadIdx.x, wid = tid >> 5, lane = tid & 31;
    int bn = blockIdx.x * GBN, bm = blockIdx.y * GBM;
    int wm = (wid & 3) * 32;
    int wn = (wid >> 2) * 64;

    // per buf (32KB): A@0, B@16K; bufs at 0 / 32K
    auto prefetch = [&](int buf, int k0) {
        uint32_t base = s0 + (uint32_t)buf * 32768u;
#pragma unroll
        for (int i = 0; i < 4; i++) {
            int idx = tid + i * 256;
            int row = idx >> 3; int ch = (idx & 7) * 16;
            uint32_t sw = swz((uint32_t)(row * 128 + ch));
            cp16(base + sw,          (const char*)Ah + ((size_t)(bm + row) * K + k0) * 2 + ch);
            cp16(base + 16384u + sw, (const char*)Bh + ((size_t)(bn + row) * K + k0) * 2 + ch);
        }
        cp_commit();
    };

    prefetch(0, 0);
    prefetch(1, GBK);

    float acc[2][8][4];
#pragma unroll
    for (int i = 0; i < 2; i++)
#pragma unroll
        for (int j = 0; j < 8; j++)
#pragma unroll
            for (int c = 0; c < 4; c++) acc[i][j][c] = 0.f;

    int NK = K / GBK;
    for (int kt = 0; kt < NK; kt++) {
        int cur = kt & 1;
        if (kt == NK - 1) asm volatile("cp.async.wait_group 0;" ::: "memory");
        else              asm volatile("cp.async.wait_group 1;" ::: "memory");
        __syncthreads();

        uint32_t base = s0 + (uint32_t)cur * 32768u;
#pragma unroll
        for (int ks = 0; ks < 4; ks++) {
            int kb = ks * 32 + ((lane >> 4) << 4);
            uint32_t ah[2][4];
#pragma unroll
            for (int i = 0; i < 2; i++) {
                uint32_t sw = swz((uint32_t)((wm + i * 16 + (lane & 15)) * 128 + kb));
                ldm_x4(ah[i], base + sw);
            }
            uint32_t bh[4][4];
#pragma unroll
            for (int j = 0; j < 4; j++) {
                uint32_t sw = swz((uint32_t)((wn + j * 16 + (lane & 15)) * 128 + kb));
                ldm_x4(bh[j], base + 16384u + sw);
            }
#pragma unroll
            for (int i = 0; i < 2; i++)
#pragma unroll
                for (int j2 = 0; j2 < 8; j2++) {
                    int jj = j2 >> 1, e = j2 & 1;
                    mma16816(acc[i][j2], ah[i], bh[jj][e], bh[jj][2 + e]);
                }
        }
        __syncthreads();
        if (kt + 2 < NK) prefetch(cur, (kt + 2) * GBK);
    }

    // epilogue: stage fp32 through smem (aliases tiles; stage region = 67.6KB)
    float* stg = (float*)(smem + (s0 - sb));
#pragma unroll
    for (int i = 0; i < 2; i++)
#pragma unroll
        for (int j2 = 0; j2 < 8; j2++) {
            int r0 = wm + i * 16 + (lane >> 2);
            int c0 = wn + j2 * 8 + 2 * (lane & 3);
            stg[r0 * 132 + c0]           = acc[i][j2][0];
            stg[r0 * 132 + c0 + 1]       = acc[i][j2][1];
            stg[(r0 + 8) * 132 + c0]     = acc[i][j2][2];
            stg[(r0 + 8) * 132 + c0 + 1] = acc[i][j2][3];
        }
    __syncthreads();
#pragma unroll
    for (int i = 0; i < 64; i++) {
        int idx = tid + i * 256;
        int rr = idx >> 7, cc = idx & 127;
        int gr = bm + rr, gc = bn + cc;
        float v = stg[rr * 132 + cc];
        if (res) v += res[(size_t)gr * N + gc];
        Cf[(size_t)gr * N + gc] = v;
    }
}

// ---------------- bucket softmax + extended q'/k' build (bf16) + loss --------------
__global__ void build_ext_k(const float* __restrict__ Whq, const float* __restrict__ Whk) {
    int wg   = blockIdx.x * 4 + (threadIdx.x >> 5);
    int lane = threadIdx.x & 31;
    int t = wg >> 4, h = wg & 15;
    int b = t >> 11, s = t & 2047;
    const float* q = g_q + (size_t)t * D_ + h * DH_;
    const float* k = g_k + (size_t)t * D_ + h * DH_;
    float ql = 0.f, kl = 0.f;
#pragma unroll 8
    for (int f = 0; f < DH_; f++) {
        float qv = q[f], kv = k[f];
        ql += qv * Whq[(h * DH_ + f) * NB_ + lane];
        kl += kv * Whk[(h * DH_ + f) * NB_ + lane];
    }
    float mq = ql, mk = kl;
#pragma unroll
    for (int o = 16; o; o >>= 1) {
        mq = fmaxf(mq, __shfl_xor_sync(0xffffffffu, mq, o));
        mk = fmaxf(mk, __shfl_xor_sync(0xffffffffu, mk, o));
    }
    float eq = __expf(ql - mq), ek = __expf(kl - mk);
    float sq = eq, sk = ek;
#pragma unroll
    for (int o = 16; o; o >>= 1) {
        sq += __shfl_xor_sync(0xffffffffu, sq, o);
        sk += __shfl_xor_sync(0xffffffffu, sk, o);
    }
    float qb = eq / sq, kb = ek / sk;
    size_t base = ((size_t)(b * H_ + h) * S_ + s) * DE_;
    __nv_bfloat16* qe = g_qeb + base;
    __nv_bfloat16* ke = g_keb + base;
    qe[64 + lane] = __float2bfloat16(0.1f * qb);   // cluster weight folded into q'
    ke[64 + lane] = __float2bfloat16(kb);
    qe[lane]      = __float2bfloat16(0.125f * q[lane]);
    qe[lane + 32] = __float2bfloat16(0.125f * q[lane + 32]);
    ke[lane]      = __float2bfloat16(k[lane]);
    ke[lane + 32] = __float2bfloat16(k[lane + 32]);
    atomicAdd(&g_mq[h * NB_ + lane], qb);
    atomicAdd(&g_mk[h * NB_ + lane], kb);
}

// ================= HMMA flash attention ============================================
#define FQM 128
__global__ void __launch_bounds__(256) fa_k() {
    extern __shared__ char smem[];
    uint32_t sb = smem_u32(smem);
    uint32_t s0 = (sb + 1023u) & ~1023u;
    uint32_t Q0 = s0, Q1 = s0 + 16384u;            // Q content / bucket subtiles
    uint32_t KV = s0 + 32768u;                     // 2 x 24KB: K0,K1,Vt per buffer
    int tid = threadIdx.x, wid = tid >> 5, lane = tid & 31;
    int blk = blockIdx.x;
    int qt = blk & 15, h = (blk >> 4) & 15, b = blk >> 8;
    int bh = b * H_ + h;
    int t0q = b * S_ + qt * FQM;

    const char* qsrc = (const char*)(g_qeb + ((size_t)bh * S_ + qt * FQM) * DE_);
    const char* ksrc0 = (const char*)(g_keb + (size_t)bh * S_ * DE_);
    const char* vsrc0 = (const char*)(g_vt + (size_t)bh * DH_ * S_);

#pragma unroll
    for (int i = 0; i < 6; i++) {
        int idx = tid + i * 256;
        int row = idx / 12, c = idx - row * 12;
        uint32_t dst = (c < 8) ? (Q0 + swz((uint32_t)(row * 128 + c * 16)))
                               : (Q1 + swz((uint32_t)(row * 128 + (c - 8) * 16)));
        cp16(dst, qsrc + (size_t)row * (DE_ * 2) + c * 16);
    }
    cp_commit();

    auto prefetch = [&](int buf, int kt) {
        uint32_t base = KV + (uint32_t)buf * 24576u;
        const char* ks = ksrc0 + (size_t)(kt * 64) * (DE_ * 2);
#pragma unroll
        for (int i = 0; i < 3; i++) {
            int idx = tid + i * 256;
            int row = idx / 12, c = idx - row * 12;
            uint32_t dst = (c < 8) ? (base + swz((uint32_t)(row * 128 + c * 16)))
                                   : (base + 8192u + swz((uint32_t)(row * 128 + (c - 8) * 16)));
            cp16(dst, ks + (size_t)row * (DE_ * 2) + c * 16);
        }
#pragma unroll
        for (int i = 0; i < 2; i++) {
            int idx = tid + i * 256;
            int row = idx >> 3, c = idx & 7;
            cp16(base + 16384u + swz((uint32_t)(row * 128 + c * 16)),
                 vsrc0 + (size_t)row * (S_ * 2) + kt * 128 + c * 16);
        }
        cp_commit();
    };

    prefetch(0, 0);
    asm volatile("cp.async.wait_group 1;" ::: "memory");
    __syncthreads();

    uint32_t qf[6][4];
#pragma unroll
    for (int ks = 0; ks < 6; ks++) {
        uint32_t base = (ks < 4) ? Q0 : Q1;
        int kb = ((ks < 4) ? ks * 32 : (ks - 4) * 32) + ((lane >> 4) << 4);
        ldm_x4(qf[ks], base + swz((uint32_t)((wid * 16 + (lane & 15)) * 128 + kb)));
    }

    float o[8][4];
#pragma unroll
    for (int j = 0; j < 8; j++)
#pragma unroll
        for (int c = 0; c < 4; c++) o[j][c] = 0.f;
    float mrow[2] = {-1e30f, -1e30f}, lrow[2] = {0.f, 0.f};

    const int NT = S_ / 64;
    for (int kt = 0; kt < NT; kt++) {
        int cur = kt & 1;
        if (kt + 1 < NT) { prefetch(cur ^ 1, kt + 1); asm volatile("cp.async.wait_group 1;" ::: "memory"); }
        else             { asm volatile("cp.async.wait_group 0;" ::: "memory"); }
        __syncthreads();

        uint32_t kbase = KV + (uint32_t)cur * 24576u;

        float s[8][4];
#pragma unroll
        for (int j = 0; j < 8; j++)
#pragma unroll
            for (int c = 0; c < 4; c++) s[j][c] = 0.f;
#pragma unroll
        for (int ks = 0; ks < 6; ks++) {
            uint32_t base = (ks < 4) ? kbase : (kbase + 8192u);
            int kb = ((ks < 4) ? ks * 32 : (ks - 4) * 32) + ((lane >> 4) << 4);
            uint32_t bf[4][4];
#pragma unroll
            for (int j = 0; j < 4; j++)
                ldm_x4(bf[j], base + swz((uint32_t)((j * 16 + (lane & 15)) * 128 + kb)));
#pragma unroll
            for (int j2 = 0; j2 < 8; j2++) {
                int jj = j2 >> 1, e = j2 & 1;
                mma16816(s[j2], qf[ks], bf[jj][e], bf[jj][2 + e]);
            }
        }

        float fac[2];
#pragma unroll
        for (int hf = 0; hf < 2; hf++) {
            float mt = -1e30f;
#pragma unroll
            for (int j = 0; j < 8; j++)
                mt = fmaxf(mt, fmaxf(s[j][2 * hf], s[j][2 * hf + 1]));
            mt = fmaxf(mt, __shfl_xor_sync(0xffffffffu, mt, 1));
            mt = fmaxf(mt, __shfl_xor_sync(0xffffffffu, mt, 2));
            float mn = fmaxf(mrow[hf], mt);
            fac[hf] = __expf(mrow[hf] - mn);
            float ps = 0.f;
#pragma unroll
            for (int j = 0; j < 8; j++) {
                float p0 = __expf(s[j][2 * hf]     - mn);
                float p1 = __expf(s[j][2 * hf + 1] - mn);
                s[j][2 * hf] = p0; s[j][2 * hf + 1] = p1;
                ps += p0 + p1;
            }
            ps += __shfl_xor_sync(0xffffffffu, ps, 1);
            ps += __shfl_xor_sync(0xffffffffu, ps, 2);
            lrow[hf] = lrow[hf] * fac[hf] + ps;
            mrow[hf] = mn;
        }
#pragma unroll
        for (int j = 0; j < 8; j++) {
            o[j][0] *= fac[0]; o[j][1] *= fac[0];
            o[j][2] *= fac[1]; o[j][3] *= fac[1];
        }

        uint32_t pf[4][4];
#pragma unroll
        for (int kb2 = 0; kb2 < 4; kb2++) {
            pf[kb2][0] = packbf(s[2 * kb2][0],     s[2 * kb2][1]);
            pf[kb2][1] = packbf(s[2 * kb2][2],     s[2 * kb2][3]);
            pf[kb2][2] = packbf(s[2 * kb2 + 1][0], s[2 * kb2 + 1][1]);
            pf[kb2][3] = packbf(s[2 * kb2 + 1][2], s[2 * kb2 + 1][3]);
        }

        uint32_t vbase = kbase + 16384u;
#pragma unroll
        for (int kb2 = 0; kb2 < 4; kb2++) {
            int kb = kb2 * 32 + ((lane >> 4) << 4);
            uint32_t bf[4][4];
#pragma unroll
            for (int j = 0; j < 4; j++)
                ldm_x4(bf[j], vbase + swz((uint32_t)((j * 16 + (lane & 15)) * 128 + kb)));
#pragma unroll
            for (int j2 = 0; j2 < 8; j2++) {
                int jj = j2 >> 1, e = j2 & 1;
                mma16816(o[j2], pf[kb2], bf[jj][e], bf[jj][2 + e]);
            }
        }
        __syncthreads();
    }

    // ---- write O (plain bf16; Wo GEMM is plain now) ----
    float inv0 = 1.f / lrow[0], inv1 = 1.f / lrow[1];
#pragma unroll
    for (int j2 = 0; j2 < 8; j2++) {
        int col = h * DH_ + j2 * 8 + 2 * (lane & 3);
#pragma unroll
        for (int hf = 0; hf < 2; hf++) {
            int row = t0q + wid * 16 + (lane >> 2) + hf * 8;
            float iv = hf ? inv1 : inv0;
            *(__nv_bfloat162*)&g_aoh[(size_t)row * D_ + col] =
                __floats2bfloat162_rn(o[j2][2 * hf] * iv, o[j2][2 * hf + 1] * iv);
        }
    }
}

// ---------------- auxiliary loss ----------------------------------------------------
__global__ void loss_k(float* out, int do_write) {
    int tid = threadIdx.x;
    float vq = g_mq[tid] * (1.f / NTOK), vk = g_mk[tid] * (1.f / NTOK);
    float s = vq * vq + vk * vk;
#pragma unroll
    for (int off = 16; off; off >>= 1) s += __shfl_xor_sync(0xffffffffu, s, off);
    __shared__ float rs[16];
    if ((tid & 31) == 0) rs[tid >> 5] = s;
    __syncthreads();
    if (tid == 0) {
        float a = 0.f;
        for (int i = 0; i < 16; i++) a += rs[i];
        if (do_write) out[0] = 0.5f * NB_ * (a / H_);
    }
}

// ---------------- launch -----------------------------------------------------------
extern "C" void kernel_launch(void* const* d_in, const int* in_sizes, int n_in,
                              void* d_out, int out_size) {
    const float* inputs = (const float*)d_in[0];
    const float* ln1g   = (const float*)d_in[1];
    const float* ln1b   = (const float*)d_in[2];
    const float* Wq     = (const float*)d_in[3];
    const float* Wk     = (const float*)d_in[4];
    const float* Wv     = (const float*)d_in[5];
    const float* Whq    = (const float*)d_in[6];
    const float* Whk    = (const float*)d_in[7];
    const float* Wo     = (const float*)d_in[8];
    const float* ln2g   = (const float*)d_in[9];
    const float* ln2b   = (const float*)d_in[10];
    const float* W1     = (const float*)d_in[11];
    const float* b1     = (const float*)d_in[12];
    const float* W2     = (const float*)d_in[13];
    const float* b2     = (const float*)d_in[14];
    float* out = (float*)d_out;

    float *q, *k, *v, *xres;
    __nv_bfloat16 *xh, *aoh, *yh, *yl, *hh, *hl;
    __nv_bfloat16 *wqt, *wkt, *wvt, *wot, *w1h, *w1l, *w2h, *w2l;
    cudaGetSymbolAddress((void**)&q,    g_q);
    cudaGetSymbolAddress((void**)&k,    g_k);
    cudaGetSymbolAddress((void**)&v,    g_v);
    cudaGetSymbolAddress((void**)&xres, g_xres);
    cudaGetSymbolAddress((void**)&xh,   g_xh);
    cudaGetSymbolAddress((void**)&aoh,  g_aoh);
    cudaGetSymbolAddress((void**)&yh,   g_yh);
    cudaGetSymbolAddress((void**)&yl,   g_yl);
    cudaGetSymbolAddress((void**)&hh,   g_hh);
    cudaGetSymbolAddress((void**)&hl,   g_hl);
    cudaGetSymbolAddress((void**)&wqt,  g_WqT);
    cudaGetSymbolAddress((void**)&wkt,  g_WkT);
    cudaGetSymbolAddress((void**)&wvt,  g_WvT);
    cudaGetSymbolAddress((void**)&wot,  g_WoT);
    cudaGetSymbolAddress((void**)&w1h,  g_W1Th); cudaGetSymbolAddress((void**)&w1l, g_W1Tl);
    cudaGetSymbolAddress((void**)&w2h,  g_W2Th); cudaGetSymbolAddress((void**)&w2l, g_W2Tl);

    zero_sums_k<<<1, 512>>>();

    dim3 tb(32, 8);
    transpose_bf_k<<<dim3(D_ / 32, D_ / 32),   tb>>>(Wq, wqt, nullptr, D_, D_);
    transpose_bf_k<<<dim3(D_ / 32, D_ / 32),   tb>>>(Wk, wkt, nullptr, D_, D_);
    transpose_bf_k<<<dim3(D_ / 32, D_ / 32),   tb>>>(Wv, wvt, nullptr, D_, D_);
    transpose_bf_k<<<dim3(D_ / 32, D_ / 32),   tb>>>(Wo, wot, nullptr, D_, D_);
    transpose_bf_k<<<dim3(D_ / 32, MLP_ / 32), tb>>>(W1, w1h, w1l, D_, MLP_);
    transpose_bf_k<<<dim3(MLP_ / 32, D_ / 32), tb>>>(W2, w2h, w2l, MLP_, D_);

    ln_k<<<NTOK, 256>>>(inputs, ln1g, ln1b, xh, nullptr);

    int gsmem  = 1024 + 2 * 65536;               // split-3 kernel
    int gpsmem = 1024 + 128 * 132 * 4;           // plain kernel (stage > 2x32KB tiles)
    cudaFuncSetAttribute(hgemm_k,   cudaFuncAttributeMaxDynamicSharedMemorySize, gsmem);
    cudaFuncSetAttribute(hgemm_p_k, cudaFuncAttributeMaxDynamicSharedMemorySize, gpsmem);

    dim3 gqkv(D_ / GBN, NTOK / GBM);       // (8, 32)
    hgemm_p_k<<<gqkv, 256, gpsmem>>>(xh, wqt, q, NTOK, D_, D_, nullptr);
    hgemm_p_k<<<gqkv, 256, gpsmem>>>(xh, wkt, k, NTOK, D_, D_, nullptr);
    hgemm_p_k<<<gqkv, 256, gpsmem>>>(xh, wvt, v, NTOK, D_, D_, nullptr);

    build_ext_k<<<NTOK * H_ / 4, 128>>>(Whq, Whk);
    vt_k<<<dim3(B_ * H_, S_ / 32), tb>>>();

    int fasmem = 1024 + 32768 + 2 * 24576;   // ~82 KB
    cudaFuncSetAttribute(fa_k, cudaFuncAttributeMaxDynamicSharedMemorySize, fasmem);
    fa_k<<<B_ * H_ * (S_ / FQM), 256, fasmem>>>();

    // attn @ Wo + residual(inputs) -> xres (fp32)
    hgemm_p_k<<<gqkv, 256, gpsmem>>>(aoh, wot, xres, NTOK, D_, D_, inputs);

    ln_k<<<NTOK, 256>>>(xres, ln2g, ln2b, yh, yl);

    dim3 gm1(MLP_ / GBN, NTOK / GBM);      // (32, 32)
    hgemm_k<<<gm1, 256, gsmem>>>(yh, yl, w1h, w1l, nullptr, hh, hl,
                                 NTOK, MLP_, D_, b1, nullptr, 1);
    hgemm_k<<<gqkv, 256, gsmem>>>(hh, hl, w2h, w2l, out, nullptr, nullptr,
                                  NTOK, D_, MLP_, b2, xres, 0);

    loss_k<<<1, 512>>>(out + (size_t)NTOK * D_, (out_size > NTOK * D_) ? 1 : 0);
}

// round 14
// speedup vs baseline: 4.4578x; 1.0479x over previous
#include <cuda_runtime.h>
#include <cuda_bf16.h>
#include <math.h>
#include <stdint.h>

// Problem dims
#define B_    2
#define S_    2048
#define D_    1024
#define H_    16
#define DH_   64
#define NB_   32
#define NTOK  4096          // B_*S_
#define MLP_  4096
#define DE_   96            // extended head dim: 64 (content) + 32 (bucket)
#define DQKV  3072          // fused q|k|v row width

// ---------------- scratch (device globals; no allocations allowed) ----------------
__device__ __align__(128) float g_qkv [NTOK * DQKV];   // fused q|k|v (fp32)
__device__ __align__(128) float g_xres[NTOK * D_];
__device__ float g_mq  [H_ * NB_];
__device__ float g_mk  [H_ * NB_];

// bf16 activation buffers
__device__ __align__(128) __nv_bfloat16 g_xh [NTOK * D_];     // ln1 out (plain bf16)
__device__ __align__(128) __nv_bfloat16 g_aoh[NTOK * D_];     // attn out (plain bf16)
__device__ __align__(128) __nv_bfloat16 g_yh [NTOK * D_];     // ln2 out hi
__device__ __align__(128) __nv_bfloat16 g_yl [NTOK * D_];     // ln2 out lo
__device__ __align__(128) __nv_bfloat16 g_hh [NTOK * MLP_];   // mlp hidden hi
__device__ __align__(128) __nv_bfloat16 g_hl [NTOK * MLP_];   // mlp hidden lo
// transposed weights [N,K]: fused QKV + Wo plain bf16; W1/W2 hi/lo split
__device__ __align__(128) __nv_bfloat16 g_WqkvT[DQKV * D_];
__device__ __align__(128) __nv_bfloat16 g_WoT[D_ * D_];
__device__ __align__(128) __nv_bfloat16 g_W1Th[MLP_ * D_], g_W1Tl[MLP_ * D_];
__device__ __align__(128) __nv_bfloat16 g_W2Th[D_ * MLP_], g_W2Tl[D_ * MLP_];

// bf16 FA operands: extended q'/k' [(b*H+h)*S + s][96], V^T [(b*H+h)][dh][S]
__device__ __align__(128) __nv_bfloat16 g_qeb[NTOK * H_ * DE_];
__device__ __align__(128) __nv_bfloat16 g_keb[NTOK * H_ * DE_];
__device__ __align__(128) __nv_bfloat16 g_vt [B_ * H_ * DH_ * S_];

// ================= PTX helpers (baseline PTX only) =================================
__device__ __forceinline__ uint32_t smem_u32(const void* p) {
    uint32_t a;
    asm("{ .reg .u64 t; cvta.to.shared.u64 t, %1; cvt.u32.u64 %0, t; }" : "=r"(a) : "l"(p));
    return a;
}
__device__ __forceinline__ void cp16(uint32_t dst, const void* src) {
    asm volatile("cp.async.cg.shared.global [%0], [%1], 16;" :: "r"(dst), "l"(src));
}
__device__ __forceinline__ void cp_commit() {
    asm volatile("cp.async.commit_group;" ::: "memory");
}
__device__ __forceinline__ void ldm_x4(uint32_t* r, uint32_t a) {
    asm volatile("ldmatrix.sync.aligned.m8n8.x4.shared.b16 {%0,%1,%2,%3}, [%4];"
        : "=r"(r[0]), "=r"(r[1]), "=r"(r[2]), "=r"(r[3]) : "r"(a));
}
__device__ __forceinline__ void mma16816(float* d, const uint32_t* a, uint32_t b0, uint32_t b1) {
    asm volatile("mma.sync.aligned.m16n8k16.row.col.f32.bf16.bf16.f32 "
        "{%0,%1,%2,%3}, {%4,%5,%6,%7}, {%8,%9}, {%0,%1,%2,%3};"
        : "+f"(d[0]), "+f"(d[1]), "+f"(d[2]), "+f"(d[3])
        : "r"(a[0]), "r"(a[1]), "r"(a[2]), "r"(a[3]), "r"(b0), "r"(b1));
}
__device__ __forceinline__ void split_bf(float v, __nv_bfloat16& hi, __nv_bfloat16& lo) {
    hi = __float2bfloat16(v);
    lo = __float2bfloat16(v - __bfloat162float(hi));
}
__device__ __forceinline__ uint32_t packbf(float a, float b) {
    __nv_bfloat162 t = __floats2bfloat162_rn(a, b);
    return *(uint32_t*)&t;
}
__device__ __forceinline__ uint32_t swz(uint32_t off) { return off ^ ((off >> 3) & 0x70u); }

// ---------------- zero the loss accumulators ---------------------------------------
__global__ void zero_sums_k() {
    int i = threadIdx.x;
    if (i < H_ * NB_) { g_mq[i] = 0.f; g_mk[i] = 0.f; }
}

// ---------------- weight transpose + bf16 (optional hi/lo): W[K,N] -> WT[N,K] ------
__global__ void transpose_bf_k(const float* __restrict__ W,
                               __nv_bfloat16* __restrict__ WTh,
                               __nv_bfloat16* __restrict__ WTl, int K, int N) {
    __shared__ float t[32][33];
    int k0 = blockIdx.x * 32, n0 = blockIdx.y * 32;
    int tx = threadIdx.x, ty = threadIdx.y;   // 32 x 8
#pragma unroll
    for (int i = 0; i < 32; i += 8)
        t[ty + i][tx] = W[(size_t)(k0 + ty + i) * N + n0 + tx];
    __syncthreads();
#pragma unroll
    for (int i = 0; i < 32; i += 8) {
        float v = t[tx][ty + i];
        size_t o = (size_t)(n0 + ty + i) * K + k0 + tx;
        if (WTl) {
            __nv_bfloat16 hi, lo; split_bf(v, hi, lo);
            WTh[o] = hi; WTl[o] = lo;
        } else {
            WTh[o] = __float2bfloat16(v);
        }
    }
}

// ---------------- V transpose per head: g_qkv[token][2048+h*64+d] -> g_vt bf16 -----
__global__ void vt_k() {
    __shared__ float t[32][72];
    int bh = blockIdx.x;               // 0..31
    int s0 = blockIdx.y * 32;
    int b = bh >> 4, h = bh & 15;
    int tx = threadIdx.x, ty = threadIdx.y;  // 32 x 8
#pragma unroll
    for (int i = 0; i < 4; i++) {
        int s = ty + i * 8;
        const float* src = g_qkv + (size_t)(b * S_ + s0 + s) * DQKV + 2048 + h * DH_;
        t[s][tx]      = src[tx];
        t[s][tx + 32] = src[tx + 32];
    }
    __syncthreads();
#pragma unroll
    for (int i = 0; i < 8; i++) {
        int d = ty + i * 8;            // 0..63
        g_vt[((size_t)bh * DH_ + d) * S_ + s0 + tx] = __float2bfloat16(t[tx][d]);
    }
}

// ---------------- layernorm: bf16 out (optional lo) --------------------------------
__global__ void ln_k(const float* __restrict__ in, const float* __restrict__ g,
                     const float* __restrict__ b,
                     __nv_bfloat16* __restrict__ oh, __nv_bfloat16* __restrict__ ol) {
    int t = blockIdx.x, tid = threadIdx.x;
    const float* x = in + (size_t)t * D_;
    float v[4]; float s = 0.f, s2 = 0.f;
#pragma unroll
    for (int i = 0; i < 4; i++) { v[i] = x[tid + i * 256]; s += v[i]; s2 += v[i] * v[i]; }
#pragma unroll
    for (int o = 16; o; o >>= 1) {
        s  += __shfl_xor_sync(0xffffffffu, s,  o);
        s2 += __shfl_xor_sync(0xffffffffu, s2, o);
    }
    __shared__ float rs[8], rs2[8];
    __shared__ float mu_s, rstd_s;
    int w = tid >> 5, l = tid & 31;
    if (l == 0) { rs[w] = s; rs2[w] = s2; }
    __syncthreads();
    if (tid == 0) {
        float a = 0.f, a2 = 0.f;
        for (int i = 0; i < 8; i++) { a += rs[i]; a2 += rs2[i]; }
        float mu = a * (1.f / D_);
        float var = a2 * (1.f / D_) - mu * mu;
        mu_s = mu; rstd_s = rsqrtf(var + 1e-6f);
    }
    __syncthreads();
    float mu = mu_s, rstd = rstd_s;
#pragma unroll
    for (int i = 0; i < 4; i++) {
        int c = tid + i * 256;
        float vv = (v[i] - mu) * rstd * g[c] + b[c];
        if (ol) {
            __nv_bfloat16 hi, lo; split_bf(vv, hi, lo);
            oh[(size_t)t * D_ + c] = hi;
            ol[(size_t)t * D_ + c] = lo;
        } else {
            oh[(size_t)t * D_ + c] = __float2bfloat16(vv);
        }
    }
}

#define GBM 128
#define GBN 128
#define GBK 64

// ================= HMMA bf16 plain GEMM (fused QKV / Wo path) ======================
// 128x128 tile, single MMA per term, 32KB/buffer.
__global__ void __launch_bounds__(256) hgemm_p_k(
    const __nv_bfloat16* __restrict__ Ah, const __nv_bfloat16* __restrict__ Bh,
    float* __restrict__ Cf, int M, int N, int K,
    const float* __restrict__ res)
{
    extern __shared__ char smem[];
    uint32_t sb = smem_u32(smem);
    uint32_t s0 = (sb + 1023u) & ~1023u;
    int tid = threadIdx.x, wid = tid >> 5, lane = tid & 31;
    int bn = blockIdx.x * GBN, bm = blockIdx.y * GBM;
    int wm = (wid & 3) * 32;
    int wn = (wid >> 2) * 64;

    auto prefetch = [&](int buf, int k0) {
        uint32_t base = s0 + (uint32_t)buf * 32768u;
#pragma unroll
        for (int i = 0; i < 4; i++) {
            int idx = tid + i * 256;
            int row = idx >> 3; int ch = (idx & 7) * 16;
            uint32_t sw = swz((uint32_t)(row * 128 + ch));
            cp16(base + sw,          (const char*)Ah + ((size_t)(bm + row) * K + k0) * 2 + ch);
            cp16(base + 16384u + sw, (const char*)Bh + ((size_t)(bn + row) * K + k0) * 2 + ch);
        }
        cp_commit();
    };

    prefetch(0, 0);
    prefetch(1, GBK);

    float acc[2][8][4];
#pragma unroll
    for (int i = 0; i < 2; i++)
#pragma unroll
        for (int j = 0; j < 8; j++)
#pragma unroll
            for (int c = 0; c < 4; c++) acc[i][j][c] = 0.f;

    int NK = K / GBK;
    for (int kt = 0; kt < NK; kt++) {
        int cur = kt & 1;
        if (kt == NK - 1) asm volatile("cp.async.wait_group 0;" ::: "memory");
        else              asm volatile("cp.async.wait_group 1;" ::: "memory");
        __syncthreads();

        uint32_t base = s0 + (uint32_t)cur * 32768u;
#pragma unroll
        for (int ks = 0; ks < 4; ks++) {
            int kb = ks * 32 + ((lane >> 4) << 4);
            uint32_t ah[2][4];
#pragma unroll
            for (int i = 0; i < 2; i++) {
                uint32_t sw = swz((uint32_t)((wm + i * 16 + (lane & 15)) * 128 + kb));
                ldm_x4(ah[i], base + sw);
            }
            uint32_t bh[4][4];
#pragma unroll
            for (int j = 0; j < 4; j++) {
                uint32_t sw = swz((uint32_t)((wn + j * 16 + (lane & 15)) * 128 + kb));
                ldm_x4(bh[j], base + 16384u + sw);
            }
#pragma unroll
            for (int i = 0; i < 2; i++)
#pragma unroll
                for (int j2 = 0; j2 < 8; j2++) {
                    int jj = j2 >> 1, e = j2 & 1;
                    mma16816(acc[i][j2], ah[i], bh[jj][e], bh[jj][2 + e]);
                }
        }
        __syncthreads();
        if (kt + 2 < NK) prefetch(cur, (kt + 2) * GBK);
    }

    float* stg = (float*)(smem + (s0 - sb));
#pragma unroll
    for (int i = 0; i < 2; i++)
#pragma unroll
        for (int j2 = 0; j2 < 8; j2++) {
            int r0 = wm + i * 16 + (lane >> 2);
            int c0 = wn + j2 * 8 + 2 * (lane & 3);
            stg[r0 * 132 + c0]           = acc[i][j2][0];
            stg[r0 * 132 + c0 + 1]       = acc[i][j2][1];
            stg[(r0 + 8) * 132 + c0]     = acc[i][j2][2];
            stg[(r0 + 8) * 132 + c0 + 1] = acc[i][j2][3];
        }
    __syncthreads();
#pragma unroll
    for (int i = 0; i < 64; i++) {
        int idx = tid + i * 256;
        int rr = idx >> 7, cc = idx & 127;
        int gr = bm + rr, gc = bn + cc;
        float v = stg[rr * 132 + cc];
        if (res) v += res[(size_t)gr * N + gc];
        Cf[(size_t)gr * N + gc] = v;
    }
}

// ================= HMMA bf16 split-3 GEMM, 128x64 tile, 2 CTAs/SM (MLP path) =======
// C = Ah·Bh + Al·Bh + Ah·Bl (fp32 accum, ~fp32 accuracy).
// Buffers: per buf (48KB): Ah@0(16K), Al@16K, Bh@32K(8K), Bl@40K. 2 bufs = 96KB.
__global__ void __launch_bounds__(256, 2) hgemm2_k(
    const __nv_bfloat16* __restrict__ Ah, const __nv_bfloat16* __restrict__ Al,
    const __nv_bfloat16* __restrict__ Bh, const __nv_bfloat16* __restrict__ Bl,
    float* __restrict__ Cf,
    __nv_bfloat16* __restrict__ Cbh, __nv_bfloat16* __restrict__ Cbl,
    int M, int N, int K,
    const float* __restrict__ bias, const float* __restrict__ res, int relu)
{
    extern __shared__ char smem[];
    uint32_t sb = smem_u32(smem);
    uint32_t s0 = (sb + 1023u) & ~1023u;
    int tid = threadIdx.x, wid = tid >> 5, lane = tid & 31;
    int bn = blockIdx.x * 64, bm = blockIdx.y * 128;
    int wm = (wid & 3) * 32;                 // warp M offset (4 warps over 128)
    int wn = (wid >> 2) * 32;                // warp N offset (2 warps over 64)

    auto prefetch = [&](int buf, int k0) {
        uint32_t base = s0 + (uint32_t)buf * 49152u;
#pragma unroll
        for (int i = 0; i < 4; i++) {        // A hi+lo: 128 rows x 8 chunks
            int idx = tid + i * 256;
            int row = idx >> 3; int ch = (idx & 7) * 16;
            uint32_t sw = swz((uint32_t)(row * 128 + ch));
            size_t ga = ((size_t)(bm + row) * K + k0) * 2 + ch;
            cp16(base + sw,          (const char*)Ah + ga);
            cp16(base + 16384u + sw, (const char*)Al + ga);
        }
#pragma unroll
        for (int i = 0; i < 2; i++) {        // B hi+lo: 64 rows x 8 chunks
            int idx = tid + i * 256;
            int row = idx >> 3; int ch = (idx & 7) * 16;
            uint32_t sw = swz((uint32_t)(row * 128 + ch));
            size_t gb = ((size_t)(bn + row) * K + k0) * 2 + ch;
            cp16(base + 32768u + sw, (const char*)Bh + gb);
            cp16(base + 40960u + sw, (const char*)Bl + gb);
        }
        cp_commit();
    };

    prefetch(0, 0);
    prefetch(1, GBK);

    float acc[2][4][4];
#pragma unroll
    for (int i = 0; i < 2; i++)
#pragma unroll
        for (int j = 0; j < 4; j++)
#pragma unroll
            for (int c = 0; c < 4; c++) acc[i][j][c] = 0.f;

    int NK = K / GBK;
    for (int kt = 0; kt < NK; kt++) {
        int cur = kt & 1;
        if (kt == NK - 1) asm volatile("cp.async.wait_group 0;" ::: "memory");
        else              asm volatile("cp.async.wait_group 1;" ::: "memory");
        __syncthreads();

        uint32_t base = s0 + (uint32_t)cur * 49152u;
#pragma unroll
        for (int ks = 0; ks < 4; ks++) {
            int kb = ks * 32 + ((lane >> 4) << 4);
            uint32_t ah[2][4], al2[2][4];
#pragma unroll
            for (int i = 0; i < 2; i++) {
                uint32_t sw = swz((uint32_t)((wm + i * 16 + (lane & 15)) * 128 + kb));
                ldm_x4(ah[i],  base + sw);
                ldm_x4(al2[i], base + 16384u + sw);
            }
            uint32_t bh2[2][4], bl2[2][4];
#pragma unroll
            for (int j = 0; j < 2; j++) {
                uint32_t sw = swz((uint32_t)((wn + j * 16 + (lane & 15)) * 128 + kb));
                ldm_x4(bh2[j], base + 32768u + sw);
                ldm_x4(bl2[j], base + 40960u + sw);
            }
#pragma unroll
            for (int i = 0; i < 2; i++)
#pragma unroll
                for (int j2 = 0; j2 < 4; j2++) {
                    int jj = j2 >> 1, e = j2 & 1;
                    uint32_t b0 = bh2[jj][e], b1 = bh2[jj][2 + e];
                    uint32_t c0 = bl2[jj][e], c1 = bl2[jj][2 + e];
                    mma16816(acc[i][j2], ah[i],  b0, b1);
                    mma16816(acc[i][j2], al2[i], b0, b1);
                    mma16816(acc[i][j2], ah[i],  c0, c1);
                }
        }
        __syncthreads();
        if (kt + 2 < NK) prefetch(cur, (kt + 2) * GBK);
    }

    // epilogue: stage fp32 through smem (aliases tiles; 128 x 68 floats = 34.8KB)
    float* stg = (float*)(smem + (s0 - sb));
#pragma unroll
    for (int i = 0; i < 2; i++)
#pragma unroll
        for (int j2 = 0; j2 < 4; j2++) {
            int r0 = wm + i * 16 + (lane >> 2);
            int c0 = wn + j2 * 8 + 2 * (lane & 3);
            stg[r0 * 68 + c0]           = acc[i][j2][0];
            stg[r0 * 68 + c0 + 1]       = acc[i][j2][1];
            stg[(r0 + 8) * 68 + c0]     = acc[i][j2][2];
            stg[(r0 + 8) * 68 + c0 + 1] = acc[i][j2][3];
        }
    __syncthreads();

    if (Cbh) {
#pragma unroll
        for (int i = 0; i < 16; i++) {       // 128 x 32 bf162 pairs
            int idx = tid + i * 256;
            int rr = idx >> 5, cp = idx & 31;
            int gr = bm + rr, gc = bn + 2 * cp;
            float v0 = stg[rr * 68 + 2 * cp];
            float v1 = stg[rr * 68 + 2 * cp + 1];
            if (bias) { v0 += bias[gc]; v1 += bias[gc + 1]; }
            if (res)  { v0 += res[(size_t)gr * N + gc]; v1 += res[(size_t)gr * N + gc + 1]; }
            if (relu) { v0 = fmaxf(v0, 0.f); v1 = fmaxf(v1, 0.f); }
            __nv_bfloat16 h0, l0, h1, l1;
            split_bf(v0, h0, l0); split_bf(v1, h1, l1);
            __nv_bfloat162 hh2; hh2.x = h0; hh2.y = h1;
            __nv_bfloat162 ll2; ll2.x = l0; ll2.y = l1;
            *(__nv_bfloat162*)&Cbh[(size_t)gr * N + gc] = hh2;
            *(__nv_bfloat162*)&Cbl[(size_t)gr * N + gc] = ll2;
        }
    } else {
#pragma unroll
        for (int i = 0; i < 32; i++) {       // 128 x 64 floats
            int idx = tid + i * 256;
            int rr = idx >> 6, cc = idx & 63;
            int gr = bm + rr, gc = bn + cc;
            float v = stg[rr * 68 + cc];
            if (bias) v += bias[gc];
            if (res)  v += res[(size_t)gr * N + gc];
            if (relu) v = fmaxf(v, 0.f);
            Cf[(size_t)gr * N + gc] = v;
        }
    }
}

// ---------------- bucket softmax + extended q'/k' build (bf16) + loss --------------
__global__ void build_ext_k(const float* __restrict__ Whq, const float* __restrict__ Whk) {
    int wg   = blockIdx.x * 4 + (threadIdx.x >> 5);
    int lane = threadIdx.x & 31;
    int t = wg >> 4, h = wg & 15;
    int b = t >> 11, s = t & 2047;
    const float* q = g_qkv + (size_t)t * DQKV + h * DH_;
    const float* k = g_qkv + (size_t)t * DQKV + 1024 + h * DH_;
    float ql = 0.f, kl = 0.f;
#pragma unroll 8
    for (int f = 0; f < DH_; f++) {
        float qv = q[f], kv = k[f];
        ql += qv * Whq[(h * DH_ + f) * NB_ + lane];
        kl += kv * Whk[(h * DH_ + f) * NB_ + lane];
    }
    float mq = ql, mk = kl;
#pragma unroll
    for (int o = 16; o; o >>= 1) {
        mq = fmaxf(mq, __shfl_xor_sync(0xffffffffu, mq, o));
        mk = fmaxf(mk, __shfl_xor_sync(0xffffffffu, mk, o));
    }
    float eq = __expf(ql - mq), ek = __expf(kl - mk);
    float sq = eq, sk = ek;
#pragma unroll
    for (int o = 16; o; o >>= 1) {
        sq += __shfl_xor_sync(0xffffffffu, sq, o);
        sk += __shfl_xor_sync(0xffffffffu, sk, o);
    }
    float qb = eq / sq, kb = ek / sk;
    size_t base = ((size_t)(b * H_ + h) * S_ + s) * DE_;
    __nv_bfloat16* qe = g_qeb + base;
    __nv_bfloat16* ke = g_keb + base;
    qe[64 + lane] = __float2bfloat16(0.1f * qb);   // cluster weight folded into q'
    ke[64 + lane] = __float2bfloat16(kb);
    qe[lane]      = __float2bfloat16(0.125f * q[lane]);
    qe[lane + 32] = __float2bfloat16(0.125f * q[lane + 32]);
    ke[lane]      = __float2bfloat16(k[lane]);
    ke[lane + 32] = __float2bfloat16(k[lane + 32]);
    atomicAdd(&g_mq[h * NB_ + lane], qb);
    atomicAdd(&g_mk[h * NB_ + lane], kb);
}

// ================= HMMA flash attention ============================================
#define FQM 128
__global__ void __launch_bounds__(256) fa_k() {
    extern __shared__ char smem[];
    uint32_t sb = smem_u32(smem);
    uint32_t s0 = (sb + 1023u) & ~1023u;
    uint32_t Q0 = s0, Q1 = s0 + 16384u;            // Q content / bucket subtiles
    uint32_t KV = s0 + 32768u;                     // 2 x 24KB: K0,K1,Vt per buffer
    int tid = threadIdx.x, wid = tid >> 5, lane = tid & 31;
    int blk = blockIdx.x;
    int qt = blk & 15, h = (blk >> 4) & 15, b = blk >> 8;
    int bh = b * H_ + h;
    int t0q = b * S_ + qt * FQM;

    const char* qsrc = (const char*)(g_qeb + ((size_t)bh * S_ + qt * FQM) * DE_);
    const char* ksrc0 = (const char*)(g_keb + (size_t)bh * S_ * DE_);
    const char* vsrc0 = (const char*)(g_vt + (size_t)bh * DH_ * S_);

#pragma unroll
    for (int i = 0; i < 6; i++) {
        int idx = tid + i * 256;
        int row = idx / 12, c = idx - row * 12;
        uint32_t dst = (c < 8) ? (Q0 + swz((uint32_t)(row * 128 + c * 16)))
                               : (Q1 + swz((uint32_t)(row * 128 + (c - 8) * 16)));
        cp16(dst, qsrc + (size_t)row * (DE_ * 2) + c * 16);
    }
    cp_commit();

    auto prefetch = [&](int buf, int kt) {
        uint32_t base = KV + (uint32_t)buf * 24576u;
        const char* ks = ksrc0 + (size_t)(kt * 64) * (DE_ * 2);
#pragma unroll
        for (int i = 0; i < 3; i++) {
            int idx = tid + i * 256;
            int row = idx / 12, c = idx - row * 12;
            uint32_t dst = (c < 8) ? (base + swz((uint32_t)(row * 128 + c * 16)))
                                   : (base + 8192u + swz((uint32_t)(row * 128 + (c - 8) * 16)));
            cp16(dst, ks + (size_t)row * (DE_ * 2) + c * 16);
        }
#pragma unroll
        for (int i = 0; i < 2; i++) {
            int idx = tid + i * 256;
            int row = idx >> 3, c = idx & 7;
            cp16(base + 16384u + swz((uint32_t)(row * 128 + c * 16)),
                 vsrc0 + (size_t)row * (S_ * 2) + kt * 128 + c * 16);
        }
        cp_commit();
    };

    prefetch(0, 0);
    asm volatile("cp.async.wait_group 1;" ::: "memory");
    __syncthreads();

    uint32_t qf[6][4];
#pragma unroll
    for (int ks = 0; ks < 6; ks++) {
        uint32_t base = (ks < 4) ? Q0 : Q1;
        int kb = ((ks < 4) ? ks * 32 : (ks - 4) * 32) + ((lane >> 4) << 4);
        ldm_x4(qf[ks], base + swz((uint32_t)((wid * 16 + (lane & 15)) * 128 + kb)));
    }

    float o[8][4];
#pragma unroll
    for (int j = 0; j < 8; j++)
#pragma unroll
        for (int c = 0; c < 4; c++) o[j][c] = 0.f;
    float mrow[2] = {-1e30f, -1e30f}, lrow[2] = {0.f, 0.f};

    const int NT = S_ / 64;
    for (int kt = 0; kt < NT; kt++) {
        int cur = kt & 1;
        if (kt + 1 < NT) { prefetch(cur ^ 1, kt + 1); asm volatile("cp.async.wait_group 1;" ::: "memory"); }
        else             { asm volatile("cp.async.wait_group 0;" ::: "memory"); }
        __syncthreads();

        uint32_t kbase = KV + (uint32_t)cur * 24576u;

        float s[8][4];
#pragma unroll
        for (int j = 0; j < 8; j++)
#pragma unroll
            for (int c = 0; c < 4; c++) s[j][c] = 0.f;
#pragma unroll
        for (int ks = 0; ks < 6; ks++) {
            uint32_t base = (ks < 4) ? kbase : (kbase + 8192u);
            int kb = ((ks < 4) ? ks * 32 : (ks - 4) * 32) + ((lane >> 4) << 4);
            uint32_t bf[4][4];
#pragma unroll
            for (int j = 0; j < 4; j++)
                ldm_x4(bf[j], base + swz((uint32_t)((j * 16 + (lane & 15)) * 128 + kb)));
#pragma unroll
            for (int j2 = 0; j2 < 8; j2++) {
                int jj = j2 >> 1, e = j2 & 1;
                mma16816(s[j2], qf[ks], bf[jj][e], bf[jj][2 + e]);
            }
        }

        float fac[2];
#pragma unroll
        for (int hf = 0; hf < 2; hf++) {
            float mt = -1e30f;
#pragma unroll
            for (int j = 0; j < 8; j++)
                mt = fmaxf(mt, fmaxf(s[j][2 * hf], s[j][2 * hf + 1]));
            mt = fmaxf(mt, __shfl_xor_sync(0xffffffffu, mt, 1));
            mt = fmaxf(mt, __shfl_xor_sync(0xffffffffu, mt, 2));
            float mn = fmaxf(mrow[hf], mt);
            fac[hf] = __expf(mrow[hf] - mn);
            float ps = 0.f;
#pragma unroll
            for (int j = 0; j < 8; j++) {
                float p0 = __expf(s[j][2 * hf]     - mn);
                float p1 = __expf(s[j][2 * hf + 1] - mn);
                s[j][2 * hf] = p0; s[j][2 * hf + 1] = p1;
                ps += p0 + p1;
            }
            ps += __shfl_xor_sync(0xffffffffu, ps, 1);
            ps += __shfl_xor_sync(0xffffffffu, ps, 2);
            lrow[hf] = lrow[hf] * fac[hf] + ps;
            mrow[hf] = mn;
        }
#pragma unroll
        for (int j = 0; j < 8; j++) {
            o[j][0] *= fac[0]; o[j][1] *= fac[0];
            o[j][2] *= fac[1]; o[j][3] *= fac[1];
        }

        uint32_t pf[4][4];
#pragma unroll
        for (int kb2 = 0; kb2 < 4; kb2++) {
            pf[kb2][0] = packbf(s[2 * kb2][0],     s[2 * kb2][1]);
            pf[kb2][1] = packbf(s[2 * kb2][2],     s[2 * kb2][3]);
            pf[kb2][2] = packbf(s[2 * kb2 + 1][0], s[2 * kb2 + 1][1]);
            pf[kb2][3] = packbf(s[2 * kb2 + 1][2], s[2 * kb2 + 1][3]);
        }

        uint32_t vbase = kbase + 16384u;
#pragma unroll
        for (int kb2 = 0; kb2 < 4; kb2++) {
            int kb = kb2 * 32 + ((lane >> 4) << 4);
            uint32_t bf[4][4];
#pragma unroll
            for (int j = 0; j < 4; j++)
                ldm_x4(bf[j], vbase + swz((uint32_t)((j * 16 + (lane & 15)) * 128 + kb)));
#pragma unroll
            for (int j2 = 0; j2 < 8; j2++) {
                int jj = j2 >> 1, e = j2 & 1;
                mma16816(o[j2], pf[kb2], bf[jj][e], bf[jj][2 + e]);
            }
        }
        __syncthreads();
    }

    float inv0 = 1.f / lrow[0], inv1 = 1.f / lrow[1];
#pragma unroll
    for (int j2 = 0; j2 < 8; j2++) {
        int col = h * DH_ + j2 * 8 + 2 * (lane & 3);
#pragma unroll
        for (int hf = 0; hf < 2; hf++) {
            int row = t0q + wid * 16 + (lane >> 2) + hf * 8;
            float iv = hf ? inv1 : inv0;
            *(__nv_bfloat162*)&g_aoh[(size_t)row * D_ + col] =
                __floats2bfloat162_rn(o[j2][2 * hf] * iv, o[j2][2 * hf + 1] * iv);
        }
    }
}

// ---------------- auxiliary loss ----------------------------------------------------
__global__ void loss_k(float* out, int do_write) {
    int tid = threadIdx.x;
    float vq = g_mq[tid] * (1.f / NTOK), vk = g_mk[tid] * (1.f / NTOK);
    float s = vq * vq + vk * vk;
#pragma unroll
    for (int off = 16; off; off >>= 1) s += __shfl_xor_sync(0xffffffffu, s, off);
    __shared__ float rs[16];
    if ((tid & 31) == 0) rs[tid >> 5] = s;
    __syncthreads();
    if (tid == 0) {
        float a = 0.f;
        for (int i = 0; i < 16; i++) a += rs[i];
        if (do_write) out[0] = 0.5f * NB_ * (a / H_);
    }
}

// ---------------- launch -----------------------------------------------------------
extern "C" void kernel_launch(void* const* d_in, const int* in_sizes, int n_in,
                              void* d_out, int out_size) {
    const float* inputs = (const float*)d_in[0];
    const float* ln1g   = (const float*)d_in[1];
    const float* ln1b   = (const float*)d_in[2];
    const float* Wq     = (const float*)d_in[3];
    const float* Wk     = (const float*)d_in[4];
    const float* Wv     = (const float*)d_in[5];
    const float* Whq    = (const float*)d_in[6];
    const float* Whk    = (const float*)d_in[7];
    const float* Wo     = (const float*)d_in[8];
    const float* ln2g   = (const float*)d_in[9];
    const float* ln2b   = (const float*)d_in[10];
    const float* W1     = (const float*)d_in[11];
    const float* b1     = (const float*)d_in[12];
    const float* W2     = (const float*)d_in[13];
    const float* b2     = (const float*)d_in[14];
    float* out = (float*)d_out;

    float *qkv, *xres;
    __nv_bfloat16 *xh, *aoh, *yh, *yl, *hh, *hl;
    __nv_bfloat16 *wqkvt, *wot, *w1h, *w1l, *w2h, *w2l;
    cudaGetSymbolAddress((void**)&qkv,  g_qkv);
    cudaGetSymbolAddress((void**)&xres, g_xres);
    cudaGetSymbolAddress((void**)&xh,   g_xh);
    cudaGetSymbolAddress((void**)&aoh,  g_aoh);
    cudaGetSymbolAddress((void**)&yh,   g_yh);
    cudaGetSymbolAddress((void**)&yl,   g_yl);
    cudaGetSymbolAddress((void**)&hh,   g_hh);
    cudaGetSymbolAddress((void**)&hl,   g_hl);
    cudaGetSymbolAddress((void**)&wqkvt, g_WqkvT);
    cudaGetSymbolAddress((void**)&wot,  g_WoT);
    cudaGetSymbolAddress((void**)&w1h,  g_W1Th); cudaGetSymbolAddress((void**)&w1l, g_W1Tl);
    cudaGetSymbolAddress((void**)&w2h,  g_W2Th); cudaGetSymbolAddress((void**)&w2l, g_W2Tl);

    zero_sums_k<<<1, 512>>>();

    dim3 tb(32, 8);
    // fused QKV weight: rows 0..1023 = Wq^T, 1024..2047 = Wk^T, 2048..3071 = Wv^T
    transpose_bf_k<<<dim3(D_ / 32, D_ / 32), tb>>>(Wq, wqkvt,              nullptr, D_, D_);
    transpose_bf_k<<<dim3(D_ / 32, D_ / 32), tb>>>(Wk, wqkvt + D_ * D_,    nullptr, D_, D_);
    transpose_bf_k<<<dim3(D_ / 32, D_ / 32), tb>>>(Wv, wqkvt + 2 * D_ * D_, nullptr, D_, D_);
    transpose_bf_k<<<dim3(D_ / 32, D_ / 32), tb>>>(Wo, wot, nullptr, D_, D_);
    transpose_bf_k<<<dim3(D_ / 32, MLP_ / 32), tb>>>(W1, w1h, w1l, D_, MLP_);
    transpose_bf_k<<<dim3(MLP_ / 32, D_ / 32), tb>>>(W2, w2h, w2l, MLP_, D_);

    ln_k<<<NTOK, 256>>>(inputs, ln1g, ln1b, xh, nullptr);

    int gpsmem = 1024 + 128 * 132 * 4;           // plain kernel
    int g2smem = 1024 + 2 * 49152;               // split-3 128x64 kernel (2 CTA/SM)
    cudaFuncSetAttribute(hgemm_p_k, cudaFuncAttributeMaxDynamicSharedMemorySize, gpsmem);
    cudaFuncSetAttribute(hgemm2_k,  cudaFuncAttributeMaxDynamicSharedMemorySize, g2smem);

    // fused QKV: [NTOK, 3072] = xh @ WqkvT^T
    hgemm_p_k<<<dim3(DQKV / GBN, NTOK / GBM), 256, gpsmem>>>(xh, wqkvt, qkv,
                                                             NTOK, DQKV, D_, nullptr);

    build_ext_k<<<NTOK * H_ / 4, 128>>>(Whq, Whk);
    vt_k<<<dim3(B_ * H_, S_ / 32), tb>>>();

    int fasmem = 1024 + 32768 + 2 * 24576;   // ~82 KB
    cudaFuncSetAttribute(fa_k, cudaFuncAttributeMaxDynamicSharedMemorySize, fasmem);
    fa_k<<<B_ * H_ * (S_ / FQM), 256, fasmem>>>();

    // attn @ Wo + residual(inputs) -> xres (fp32)
    hgemm_p_k<<<dim3(D_ / GBN, NTOK / GBM), 256, gpsmem>>>(aoh, wot, xres,
                                                           NTOK, D_, D_, inputs);

    ln_k<<<NTOK, 256>>>(xres, ln2g, ln2b, yh, yl);

    // MLP1: relu(y @ W1 + b1) -> bf16 hi/lo
    hgemm2_k<<<dim3(MLP_ / 64, NTOK / 128), 256, g2smem>>>(yh, yl, w1h, w1l,
        nullptr, hh, hl, NTOK, MLP_, D_, b1, nullptr, 1);
    // MLP2: h @ W2 + b2 + xres -> out (fp32)
    hgemm2_k<<<dim3(D_ / 64, NTOK / 128), 256, g2smem>>>(hh, hl, w2h, w2l,
        out, nullptr, nullptr, NTOK, D_, MLP_, b2, xres, 0);

    loss_k<<<1, 512>>>(out + (size_t)NTOK * D_, (out_size > NTOK * D_) ? 1 : 0);
}